// round 6
// baseline (speedup 1.0000x reference)
#include <cuda_runtime.h>
#include <math.h>

// ---------------- problem constants ----------------
#define BSZ     4
#define TLEN    1024
#define DM      768
#define DI      1536
#define DS      16
#define DTR     48
#define NLAYERS 4
#define MROWS   (BSZ*TLEN)          // 4096
#define NCHUNK  16
#define CLEN    (TLEN/NCHUNK)       // 64
#define EPSV    1e-5f

// ---------------- scratch (device globals: no cudaMalloc allowed) ----------------
// offsets in floats
#define OFF_H     0L
#define OFF_XN    (OFF_H    + (long)MROWS*DM)          // 3,145,728
#define OFF_XZ    (OFF_XN   + (long)MROWS*DM)
#define OFF_XX    (OFF_XZ   + (long)MROWS*2*DI)
#define OFF_DBC   (OFF_XX   + (long)MROWS*DI)
#define OFF_DELTA (OFF_DBC  + (long)MROWS*80)
#define OFF_Y     (OFF_DELTA+ (long)MROWS*DI)
#define OFF_P     (OFF_Y    + (long)MROWS*DI)
#define OFF_Q     (OFF_P    + (long)BSZ*NCHUNK*DI*DS)
#define OFF_HS    (OFF_Q    + (long)BSZ*NCHUNK*DI*DS)
#define TOTALF    (OFF_HS   + (long)NCHUNK*BSZ*DI*DS)  // 42,795,008 floats (~171 MB)

__device__ float g_buf[TOTALF];

__device__ __forceinline__ float ex2f(float x) {
    float y; asm("ex2.approx.f32 %0, %1;" : "=f"(y) : "f"(x)); return y;
}

// ---------------- input projection: h[m,e] = inp_b[e] + sum_f x[m,f]*inp_w[e,f] ----------------
__global__ void input_proj_k(const float* __restrict__ x, const float* __restrict__ w,
                             const float* __restrict__ b, float* __restrict__ h)
{
    int m = blockIdx.x;
    __shared__ float xs[12];
    if (threadIdx.x < 12) xs[threadIdx.x] = x[m*12 + threadIdx.x];
    __syncthreads();
    for (int e = threadIdx.x; e < DM; e += 256) {
        float acc = b[e];
        const float* wr = w + e*12;
        #pragma unroll
        for (int f = 0; f < 12; f++) acc += xs[f]*wr[f];
        h[(long)m*DM + e] = acc;
    }
}

// ---------------- rmsnorm: out = x * rsqrt(mean(x^2)+eps) * w ----------------
__global__ void rmsnorm_k(const float* __restrict__ x, const float* __restrict__ w,
                          float* __restrict__ out)
{
    int m = blockIdx.x;
    const float* row = x + (long)m*DM;
    float v0 = row[threadIdx.x];
    float v1 = row[threadIdx.x + 256];
    float v2 = row[threadIdx.x + 512];
    float ss = v0*v0 + v1*v1 + v2*v2;
    #pragma unroll
    for (int o = 16; o > 0; o >>= 1) ss += __shfl_down_sync(0xffffffffu, ss, o);
    __shared__ float sred[8];
    __shared__ float s_scale;
    if ((threadIdx.x & 31) == 0) sred[threadIdx.x >> 5] = ss;
    __syncthreads();
    if (threadIdx.x == 0) {
        float tot = 0.f;
        #pragma unroll
        for (int i = 0; i < 8; i++) tot += sred[i];
        s_scale = rsqrtf(tot * (1.f/DM) + EPSV);
    }
    __syncthreads();
    float sc = s_scale;
    float* orow = out + (long)m*DM;
    orow[threadIdx.x]       = v0 * sc * w[threadIdx.x];
    orow[threadIdx.x + 256] = v1 * sc * w[threadIdx.x + 256];
    orow[threadIdx.x + 512] = v2 * sc * w[threadIdx.x + 512];
}

// ---------------- SGEMM NT: C[M,N] = A[M,K] * B[N,K]^T (128x128x8, 8x8 microtile) ----------------
// EPI: 0 = store, 1 = softplus(acc + bias[n]), 2 = C += acc (residual)
template<int EPI>
__global__ __launch_bounds__(256, 2)
void sgemm_nt(const float* __restrict__ A, const float* __restrict__ B,
              float* __restrict__ C, const float* __restrict__ bias,
              int N, int K, int lda, int ldb, int ldc)
{
    __shared__ __align__(16) float As[8][128];
    __shared__ __align__(16) float Bs[8][128];

    const int tid  = threadIdx.x;
    const int bm   = blockIdx.y * 128;
    const int bn   = blockIdx.x * 128;
    const int arow = tid >> 1;
    const int acol = (tid & 1) << 2;
    const int ty   = tid >> 4;
    const int tx   = tid & 15;

    float acc[8][8];
    #pragma unroll
    for (int i = 0; i < 8; i++)
        #pragma unroll
        for (int j = 0; j < 8; j++) acc[i][j] = 0.f;

    const float* Aptr = A + (long)(bm + arow)*lda + acol;
    const float* Bptr = B + (long)(bn + arow)*ldb + acol;
    const bool bvalid = (bn + arow) < N;

    const int nk = K >> 3;
    float4 a_reg = *(const float4*)Aptr;
    float4 b_reg = bvalid ? *(const float4*)Bptr : make_float4(0.f,0.f,0.f,0.f);

    for (int kt = 0; kt < nk; kt++) {
        As[acol+0][arow] = a_reg.x; As[acol+1][arow] = a_reg.y;
        As[acol+2][arow] = a_reg.z; As[acol+3][arow] = a_reg.w;
        Bs[acol+0][arow] = b_reg.x; Bs[acol+1][arow] = b_reg.y;
        Bs[acol+2][arow] = b_reg.z; Bs[acol+3][arow] = b_reg.w;
        __syncthreads();
        if (kt + 1 < nk) {
            a_reg = *(const float4*)(Aptr + (kt+1)*8);
            b_reg = bvalid ? *(const float4*)(Bptr + (kt+1)*8) : make_float4(0.f,0.f,0.f,0.f);
        }
        #pragma unroll
        for (int k = 0; k < 8; k++) {
            float4 a0 = *(const float4*)&As[k][ty*8];
            float4 a1 = *(const float4*)&As[k][ty*8 + 4];
            float4 b0 = *(const float4*)&Bs[k][tx*8];
            float4 b1 = *(const float4*)&Bs[k][tx*8 + 4];
            float av[8] = {a0.x,a0.y,a0.z,a0.w,a1.x,a1.y,a1.z,a1.w};
            float bv[8] = {b0.x,b0.y,b0.z,b0.w,b1.x,b1.y,b1.z,b1.w};
            #pragma unroll
            for (int i = 0; i < 8; i++)
                #pragma unroll
                for (int j = 0; j < 8; j++)
                    acc[i][j] += av[i]*bv[j];
        }
        __syncthreads();
    }

    #pragma unroll
    for (int i = 0; i < 8; i++) {
        long row = bm + ty*8 + i;
        #pragma unroll
        for (int j = 0; j < 8; j++) {
            int col = bn + tx*8 + j;
            if (col < N) {
                float v = acc[i][j];
                if (EPI == 1) {
                    v += bias[col];
                    v = (v > 20.f) ? v : log1pf(__expf(v));   // softplus
                    C[row*ldc + col] = v;
                } else if (EPI == 2) {
                    C[row*ldc + col] += v;
                } else {
                    C[row*ldc + col] = v;
                }
            }
        }
    }
}

// ---------------- depthwise causal conv (k=4) + silu, over xz[:, :DI] ----------------
__global__ void conv_silu_k(const float* __restrict__ xz, const float* __restrict__ cw,
                            const float* __restrict__ cb, float* __restrict__ xx)
{
    long idx = (long)blockIdx.x*256 + threadIdx.x;      // over MROWS*DI
    int d = (int)(idx % DI);
    long bt = idx / DI;
    int t = (int)(bt % TLEN);
    long b = bt / TLEN;
    float acc = cb[d];
    #pragma unroll
    for (int k = 0; k < 4; k++) {
        int ts = t - 3 + k;
        if (ts >= 0) acc += cw[d*4 + k] * xz[(b*TLEN + ts)*(2L*DI) + d];
    }
    float s = acc / (1.f + __expf(-acc));
    xx[idx] = s;
}

// ---------------- selective scan, phase A: per-chunk (P, Q) composition ----------------
// grid: (DI/256, NCHUNK, BSZ)
__global__ void scan_phaseA(const float* __restrict__ delta, const float* __restrict__ xx,
                            const float* __restrict__ dbc,  const float* __restrict__ A_log_l,
                            float* __restrict__ Pbuf, float* __restrict__ Qbuf)
{
    const int d = blockIdx.x*256 + threadIdx.x;
    const int c = blockIdx.y, b = blockIdx.z;
    __shared__ __align__(16) float sB[CLEN][16];
    const long rbase = (long)b*TLEN + c*CLEN;
    for (int i = threadIdx.x; i < CLEN*16; i += 256) {
        int tt = i >> 4, n = i & 15;
        sB[tt][n] = dbc[(rbase + tt)*80 + 48 + n];
    }
    __syncthreads();

    float An[16];
    #pragma unroll
    for (int n = 0; n < 16; n++)
        An[n] = -__expf(A_log_l[d*16 + n]) * 1.44269504f;   // A * log2(e)

    float P[16], Q[16];
    #pragma unroll
    for (int n = 0; n < 16; n++) { P[n] = 1.f; Q[n] = 0.f; }

    const long off = rbase*DI + d;
    const float* dp = delta + off;
    const float* xp = xx + off;

    for (int tt = 0; tt < CLEN; tt++) {
        float dl  = dp[(long)tt*DI];
        float xv  = xp[(long)tt*DI];
        float dtx = dl * xv;
        float4 b0 = *(const float4*)&sB[tt][0];
        float4 b1 = *(const float4*)&sB[tt][4];
        float4 b2 = *(const float4*)&sB[tt][8];
        float4 b3 = *(const float4*)&sB[tt][12];
        float bv[16] = {b0.x,b0.y,b0.z,b0.w, b1.x,b1.y,b1.z,b1.w,
                        b2.x,b2.y,b2.z,b2.w, b3.x,b3.y,b3.z,b3.w};
        #pragma unroll
        for (int n = 0; n < 16; n++) {
            float a = ex2f(dl * An[n]);
            P[n] *= a;
            Q[n] = a*Q[n] + dtx*bv[n];
        }
    }
    long base = (((long)b*NCHUNK + c)*DI + d) * 16;
    #pragma unroll
    for (int n = 0; n < 16; n += 4) {
        *(float4*)&Pbuf[base + n] = make_float4(P[n],P[n+1],P[n+2],P[n+3]);
        *(float4*)&Qbuf[base + n] = make_float4(Q[n],Q[n+1],Q[n+2],Q[n+3]);
    }
}

// ---------------- scan phase B: sequential chunk combine, emit chunk-entry states ----------------
__global__ void scan_phaseB(const float* __restrict__ Pbuf, const float* __restrict__ Qbuf,
                            float* __restrict__ hs)
{
    int idx = blockIdx.x*256 + threadIdx.x;   // over BSZ*DI = 6144
    int b = idx / DI, d = idx % DI;
    float h[16];
    #pragma unroll
    for (int n = 0; n < 16; n++) h[n] = 0.f;
    for (int c = 0; c < NCHUNK; c++) {
        long obase = (((long)c*BSZ + b)*DI + d) * 16;
        #pragma unroll
        for (int n = 0; n < 16; n += 4)
            *(float4*)&hs[obase + n] = make_float4(h[n],h[n+1],h[n+2],h[n+3]);
        long ibase = (((long)b*NCHUNK + c)*DI + d) * 16;
        #pragma unroll
        for (int n = 0; n < 16; n += 4) {
            float4 p = *(const float4*)&Pbuf[ibase + n];
            float4 q = *(const float4*)&Qbuf[ibase + n];
            h[n+0] = p.x*h[n+0] + q.x;
            h[n+1] = p.y*h[n+1] + q.y;
            h[n+2] = p.z*h[n+2] + q.z;
            h[n+3] = p.w*h[n+3] + q.w;
        }
    }
}

// ---------------- scan phase C: replay + y = dot(h,C) + D*x, gated by silu(z) ----------------
// grid: (DI/256, NCHUNK, BSZ)
__global__ void scan_phaseC(const float* __restrict__ delta, const float* __restrict__ xx,
                            const float* __restrict__ dbc,  const float* __restrict__ xz,
                            const float* __restrict__ A_log_l, const float* __restrict__ Dsk_l,
                            const float* __restrict__ hs, float* __restrict__ y)
{
    const int d = blockIdx.x*256 + threadIdx.x;
    const int c = blockIdx.y, b = blockIdx.z;
    __shared__ __align__(16) float sB[CLEN][16];
    __shared__ __align__(16) float sC[CLEN][16];
    const long rbase = (long)b*TLEN + c*CLEN;
    for (int i = threadIdx.x; i < CLEN*32; i += 256) {
        int tt = i >> 5, k = i & 31;
        float v = dbc[(rbase + tt)*80 + 48 + k];
        if (k < 16) sB[tt][k] = v; else sC[tt][k-16] = v;
    }
    __syncthreads();

    float An[16];
    #pragma unroll
    for (int n = 0; n < 16; n++)
        An[n] = -__expf(A_log_l[d*16 + n]) * 1.44269504f;

    float h[16];
    const float* hsp = hs + (((long)c*BSZ + b)*DI + d) * 16;
    #pragma unroll
    for (int n = 0; n < 16; n += 4) {
        float4 v = *(const float4*)&hsp[n];
        h[n] = v.x; h[n+1] = v.y; h[n+2] = v.z; h[n+3] = v.w;
    }
    const float Dv = Dsk_l[d];
    const long off = rbase*DI + d;
    const float* dp = delta + off;
    const float* xp = xx + off;
    const float* zp = xz + rbase*(2L*DI) + DI + d;
    float* yp = y + off;

    for (int tt = 0; tt < CLEN; tt++) {
        float dl  = dp[(long)tt*DI];
        float xv  = xp[(long)tt*DI];
        float dtx = dl * xv;
        float4 b0 = *(const float4*)&sB[tt][0];
        float4 b1 = *(const float4*)&sB[tt][4];
        float4 b2 = *(const float4*)&sB[tt][8];
        float4 b3 = *(const float4*)&sB[tt][12];
        float4 c0 = *(const float4*)&sC[tt][0];
        float4 c1 = *(const float4*)&sC[tt][4];
        float4 c2 = *(const float4*)&sC[tt][8];
        float4 c3 = *(const float4*)&sC[tt][12];
        float bv[16] = {b0.x,b0.y,b0.z,b0.w, b1.x,b1.y,b1.z,b1.w,
                        b2.x,b2.y,b2.z,b2.w, b3.x,b3.y,b3.z,b3.w};
        float cv[16] = {c0.x,c0.y,c0.z,c0.w, c1.x,c1.y,c1.z,c1.w,
                        c2.x,c2.y,c2.z,c2.w, c3.x,c3.y,c3.z,c3.w};
        float yacc = 0.f;
        #pragma unroll
        for (int n = 0; n < 16; n++) {
            float a = ex2f(dl * An[n]);
            h[n] = a*h[n] + dtx*bv[n];
            yacc += h[n]*cv[n];
        }
        float yd = yacc + Dv*xv;
        float zv = zp[(long)tt*(2L*DI)];
        float gate = zv / (1.f + __expf(-zv));   // silu(z)
        yp[(long)tt*DI] = yd * gate;
    }
}

// ---------------- final: rmsnorm + head in one pass ----------------
__global__ void head_k(const float* __restrict__ h, const float* __restrict__ nw,
                       const float* __restrict__ hw, const float* __restrict__ hb,
                       float* __restrict__ out)
{
    int m = blockIdx.x;
    const float* row = h + (long)m*DM;
    float ss = 0.f, dp = 0.f;
    #pragma unroll
    for (int r = 0; r < 3; r++) {
        int i = threadIdx.x + r*256;
        float v = row[i];
        ss += v*v;
        dp += v * nw[i] * hw[i];
    }
    #pragma unroll
    for (int o = 16; o > 0; o >>= 1) {
        ss += __shfl_down_sync(0xffffffffu, ss, o);
        dp += __shfl_down_sync(0xffffffffu, dp, o);
    }
    __shared__ float s_ss[8], s_dp[8];
    if ((threadIdx.x & 31) == 0) { s_ss[threadIdx.x>>5] = ss; s_dp[threadIdx.x>>5] = dp; }
    __syncthreads();
    if (threadIdx.x == 0) {
        float tss = 0.f, tdp = 0.f;
        #pragma unroll
        for (int i = 0; i < 8; i++) { tss += s_ss[i]; tdp += s_dp[i]; }
        out[m] = tdp * rsqrtf(tss * (1.f/DM) + EPSV) + hb[0];
    }
}

// ---------------- launcher ----------------
extern "C" void kernel_launch(void* const* d_in, const int* in_sizes, int n_in,
                              void* d_out, int out_size)
{
    const float* x         = (const float*)d_in[0];
    const float* inp_w     = (const float*)d_in[1];
    const float* inp_b     = (const float*)d_in[2];
    const float* in_proj_w = (const float*)d_in[3];
    const float* conv_w    = (const float*)d_in[4];
    const float* conv_b    = (const float*)d_in[5];
    const float* x_proj_w  = (const float*)d_in[6];
    const float* dt_proj_w = (const float*)d_in[7];
    const float* dt_proj_b = (const float*)d_in[8];
    const float* A_log     = (const float*)d_in[9];
    const float* D_skip    = (const float*)d_in[10];
    const float* out_proj_w= (const float*)d_in[11];
    const float* ln_w      = (const float*)d_in[12];
    const float* norm_w    = (const float*)d_in[13];
    const float* head_w    = (const float*)d_in[14];
    const float* head_b    = (const float*)d_in[15];

    float* buf = nullptr;
    cudaGetSymbolAddress((void**)&buf, g_buf);
    float* h     = buf + OFF_H;
    float* xn    = buf + OFF_XN;
    float* xz    = buf + OFF_XZ;
    float* xx    = buf + OFF_XX;
    float* dbc   = buf + OFF_DBC;
    float* delta = buf + OFF_DELTA;
    float* yb    = buf + OFF_Y;
    float* Pb    = buf + OFF_P;
    float* Qb    = buf + OFF_Q;
    float* hsb   = buf + OFF_HS;

    input_proj_k<<<MROWS, 256>>>(x, inp_w, inp_b, h);

    for (int l = 0; l < NLAYERS; l++) {
        const float* inw  = in_proj_w + (long)l*2*DI*DM;
        const float* cw   = conv_w    + (long)l*DI*4;
        const float* cb   = conv_b    + (long)l*DI;
        const float* xpw  = x_proj_w  + (long)l*80*DI;
        const float* dtw  = dt_proj_w + (long)l*DI*DTR;
        const float* dtb  = dt_proj_b + (long)l*DI;
        const float* Al   = A_log     + (long)l*DI*DS;
        const float* Dsk  = D_skip    + (long)l*DI;
        const float* opw  = out_proj_w+ (long)l*DM*DI;
        const float* lnw  = ln_w      + (long)l*DM;

        rmsnorm_k<<<MROWS, 256>>>(h, lnw, xn);

        // xz[4096,3072] = xn[4096,768] @ inw[3072,768]^T
        sgemm_nt<0><<<dim3((2*DI)/128, MROWS/128), 256>>>(xn, inw, xz, nullptr,
                                                          2*DI, DM, DM, DM, 2*DI);
        conv_silu_k<<<(MROWS*DI)/256, 256>>>(xz, cw, cb, xx);

        // dbc[4096,80] = xx[4096,1536] @ xpw[80,1536]^T
        sgemm_nt<0><<<dim3(1, MROWS/128), 256>>>(xx, xpw, dbc, nullptr,
                                                 80, DI, DI, DI, 80);
        // delta[4096,1536] = softplus(dbc[:, :48] @ dtw[1536,48]^T + dtb)
        sgemm_nt<1><<<dim3(DI/128, MROWS/128), 256>>>(dbc, dtw, delta, dtb,
                                                      DI, DTR, 80, DTR, DI);

        scan_phaseA<<<dim3(DI/256, NCHUNK, BSZ), 256>>>(delta, xx, dbc, Al, Pb, Qb);
        scan_phaseB<<<(BSZ*DI)/256, 256>>>(Pb, Qb, hsb);
        scan_phaseC<<<dim3(DI/256, NCHUNK, BSZ), 256>>>(delta, xx, dbc, xz, Al, Dsk, hsb, yb);

        // h[4096,768] += yb[4096,1536] @ opw[768,1536]^T
        sgemm_nt<2><<<dim3(DM/128, MROWS/128), 256>>>(yb, opw, h, nullptr,
                                                      DM, DI, DI, DI, DM);
    }

    head_k<<<MROWS, 256>>>(h, norm_w, head_w, head_b, (float*)d_out);
}

// round 7
// speedup vs baseline: 1.0026x; 1.0026x over previous
#include <cuda_runtime.h>
#include <math.h>

// ---------------- problem constants ----------------
#define BSZ     4
#define TLEN    1024
#define DM      768
#define DI      1536
#define DS      16
#define DTR     48
#define NLAYERS 4
#define MROWS   (BSZ*TLEN)          // 4096
#define NCHUNK  16
#define CLEN    (TLEN/NCHUNK)       // 64
#define EPSV    1e-5f

// ---------------- scratch (device globals: no cudaMalloc allowed) ----------------
// offsets in floats
#define OFF_H     0L
#define OFF_XN    (OFF_H    + (long)MROWS*DM)          // 3,145,728
#define OFF_XZ    (OFF_XN   + (long)MROWS*DM)
#define OFF_XX    (OFF_XZ   + (long)MROWS*2*DI)
#define OFF_DBC   (OFF_XX   + (long)MROWS*DI)
#define OFF_DELTA (OFF_DBC  + (long)MROWS*80)
#define OFF_Y     (OFF_DELTA+ (long)MROWS*DI)
#define OFF_P     (OFF_Y    + (long)MROWS*DI)
#define OFF_Q     (OFF_P    + (long)BSZ*NCHUNK*DI*DS)
#define OFF_HS    (OFF_Q    + (long)BSZ*NCHUNK*DI*DS)
#define TOTALF    (OFF_HS   + (long)NCHUNK*BSZ*DI*DS)  // 42,795,008 floats (~171 MB)

__device__ float g_buf[TOTALF];

__device__ __forceinline__ float ex2f(float x) {
    float y; asm("ex2.approx.f32 %0, %1;" : "=f"(y) : "f"(x)); return y;
}

// ---------------- input projection: h[m,e] = inp_b[e] + sum_f x[m,f]*inp_w[e,f] ----------------
__global__ void input_proj_k(const float* __restrict__ x, const float* __restrict__ w,
                             const float* __restrict__ b, float* __restrict__ h)
{
    int m = blockIdx.x;
    __shared__ float xs[12];
    if (threadIdx.x < 12) xs[threadIdx.x] = x[m*12 + threadIdx.x];
    __syncthreads();
    for (int e = threadIdx.x; e < DM; e += 256) {
        float acc = b[e];
        const float* wr = w + e*12;
        #pragma unroll
        for (int f = 0; f < 12; f++) acc += xs[f]*wr[f];
        h[(long)m*DM + e] = acc;
    }
}

// ---------------- rmsnorm: out = x * rsqrt(mean(x^2)+eps) * w ----------------
__global__ void rmsnorm_k(const float* __restrict__ x, const float* __restrict__ w,
                          float* __restrict__ out)
{
    int m = blockIdx.x;
    const float* row = x + (long)m*DM;
    float v0 = row[threadIdx.x];
    float v1 = row[threadIdx.x + 256];
    float v2 = row[threadIdx.x + 512];
    float ss = v0*v0 + v1*v1 + v2*v2;
    #pragma unroll
    for (int o = 16; o > 0; o >>= 1) ss += __shfl_down_sync(0xffffffffu, ss, o);
    __shared__ float sred[8];
    __shared__ float s_scale;
    if ((threadIdx.x & 31) == 0) sred[threadIdx.x >> 5] = ss;
    __syncthreads();
    if (threadIdx.x == 0) {
        float tot = 0.f;
        #pragma unroll
        for (int i = 0; i < 8; i++) tot += sred[i];
        s_scale = rsqrtf(tot * (1.f/DM) + EPSV);
    }
    __syncthreads();
    float sc = s_scale;
    float* orow = out + (long)m*DM;
    orow[threadIdx.x]       = v0 * sc * w[threadIdx.x];
    orow[threadIdx.x + 256] = v1 * sc * w[threadIdx.x + 256];
    orow[threadIdx.x + 512] = v2 * sc * w[threadIdx.x + 512];
}

// ---------------- SGEMM NT: C[M,N] = A[M,K] * B[N,K]^T (128x128x8, 8x8 microtile) ----------------
// EPI: 0 = store, 1 = softplus(acc + bias[n]), 2 = C += acc (residual)
template<int EPI>
__global__ __launch_bounds__(256, 2)
void sgemm_nt(const float* __restrict__ A, const float* __restrict__ B,
              float* __restrict__ C, const float* __restrict__ bias,
              int N, int K, int lda, int ldb, int ldc)
{
    __shared__ __align__(16) float As[8][128];
    __shared__ __align__(16) float Bs[8][128];

    const int tid  = threadIdx.x;
    const int bm   = blockIdx.y * 128;
    const int bn   = blockIdx.x * 128;
    const int arow = tid >> 1;
    const int acol = (tid & 1) << 2;
    const int ty   = tid >> 4;
    const int tx   = tid & 15;

    float acc[8][8];
    #pragma unroll
    for (int i = 0; i < 8; i++)
        #pragma unroll
        for (int j = 0; j < 8; j++) acc[i][j] = 0.f;

    const float* Aptr = A + (long)(bm + arow)*lda + acol;
    const float* Bptr = B + (long)(bn + arow)*ldb + acol;
    const bool bvalid = (bn + arow) < N;

    const int nk = K >> 3;
    float4 a_reg = *(const float4*)Aptr;
    float4 b_reg = bvalid ? *(const float4*)Bptr : make_float4(0.f,0.f,0.f,0.f);

    for (int kt = 0; kt < nk; kt++) {
        As[acol+0][arow] = a_reg.x; As[acol+1][arow] = a_reg.y;
        As[acol+2][arow] = a_reg.z; As[acol+3][arow] = a_reg.w;
        Bs[acol+0][arow] = b_reg.x; Bs[acol+1][arow] = b_reg.y;
        Bs[acol+2][arow] = b_reg.z; Bs[acol+3][arow] = b_reg.w;
        __syncthreads();
        if (kt + 1 < nk) {
            a_reg = *(const float4*)(Aptr + (kt+1)*8);
            b_reg = bvalid ? *(const float4*)(Bptr + (kt+1)*8) : make_float4(0.f,0.f,0.f,0.f);
        }
        #pragma unroll
        for (int k = 0; k < 8; k++) {
            float4 a0 = *(const float4*)&As[k][ty*8];
            float4 a1 = *(const float4*)&As[k][ty*8 + 4];
            float4 b0 = *(const float4*)&Bs[k][tx*8];
            float4 b1 = *(const float4*)&Bs[k][tx*8 + 4];
            float av[8] = {a0.x,a0.y,a0.z,a0.w,a1.x,a1.y,a1.z,a1.w};
            float bv[8] = {b0.x,b0.y,b0.z,b0.w,b1.x,b1.y,b1.z,b1.w};
            #pragma unroll
            for (int i = 0; i < 8; i++)
                #pragma unroll
                for (int j = 0; j < 8; j++)
                    acc[i][j] += av[i]*bv[j];
        }
        __syncthreads();
    }

    #pragma unroll
    for (int i = 0; i < 8; i++) {
        long row = bm + ty*8 + i;
        #pragma unroll
        for (int j = 0; j < 8; j++) {
            int col = bn + tx*8 + j;
            if (col < N) {
                float v = acc[i][j];
                if (EPI == 1) {
                    v += bias[col];
                    v = (v > 20.f) ? v : log1pf(__expf(v));   // softplus
                    C[row*ldc + col] = v;
                } else if (EPI == 2) {
                    C[row*ldc + col] += v;
                } else {
                    C[row*ldc + col] = v;
                }
            }
        }
    }
}

// ---------------- depthwise causal conv (k=4) + silu, over xz[:, :DI] ----------------
__global__ void conv_silu_k(const float* __restrict__ xz, const float* __restrict__ cw,
                            const float* __restrict__ cb, float* __restrict__ xx)
{
    long idx = (long)blockIdx.x*256 + threadIdx.x;      // over MROWS*DI
    int d = (int)(idx % DI);
    long bt = idx / DI;
    int t = (int)(bt % TLEN);
    long b = bt / TLEN;
    float acc = cb[d];
    #pragma unroll
    for (int k = 0; k < 4; k++) {
        int ts = t - 3 + k;
        if (ts >= 0) acc += cw[d*4 + k] * xz[(b*TLEN + ts)*(2L*DI) + d];
    }
    float s = acc / (1.f + __expf(-acc));
    xx[idx] = s;
}

// ---------------- selective scan, phase A: per-chunk (P, Q) composition ----------------
// grid: (DI/256, NCHUNK, BSZ)
__global__ void scan_phaseA(const float* __restrict__ delta, const float* __restrict__ xx,
                            const float* __restrict__ dbc,  const float* __restrict__ A_log_l,
                            float* __restrict__ Pbuf, float* __restrict__ Qbuf)
{
    const int d = blockIdx.x*256 + threadIdx.x;
    const int c = blockIdx.y, b = blockIdx.z;
    __shared__ __align__(16) float sB[CLEN][16];
    const long rbase = (long)b*TLEN + c*CLEN;
    for (int i = threadIdx.x; i < CLEN*16; i += 256) {
        int tt = i >> 4, n = i & 15;
        sB[tt][n] = dbc[(rbase + tt)*80 + 48 + n];
    }
    __syncthreads();

    float An[16];
    #pragma unroll
    for (int n = 0; n < 16; n++)
        An[n] = -__expf(A_log_l[d*16 + n]) * 1.44269504f;   // A * log2(e)

    float P[16], Q[16];
    #pragma unroll
    for (int n = 0; n < 16; n++) { P[n] = 1.f; Q[n] = 0.f; }

    const long off = rbase*DI + d;
    const float* dp = delta + off;
    const float* xp = xx + off;

    for (int tt = 0; tt < CLEN; tt++) {
        float dl  = dp[(long)tt*DI];
        float xv  = xp[(long)tt*DI];
        float dtx = dl * xv;
        float4 b0 = *(const float4*)&sB[tt][0];
        float4 b1 = *(const float4*)&sB[tt][4];
        float4 b2 = *(const float4*)&sB[tt][8];
        float4 b3 = *(const float4*)&sB[tt][12];
        float bv[16] = {b0.x,b0.y,b0.z,b0.w, b1.x,b1.y,b1.z,b1.w,
                        b2.x,b2.y,b2.z,b2.w, b3.x,b3.y,b3.z,b3.w};
        #pragma unroll
        for (int n = 0; n < 16; n++) {
            float a = ex2f(dl * An[n]);
            P[n] *= a;
            Q[n] = a*Q[n] + dtx*bv[n];
        }
    }
    long base = (((long)b*NCHUNK + c)*DI + d) * 16;
    #pragma unroll
    for (int n = 0; n < 16; n += 4) {
        *(float4*)&Pbuf[base + n] = make_float4(P[n],P[n+1],P[n+2],P[n+3]);
        *(float4*)&Qbuf[base + n] = make_float4(Q[n],Q[n+1],Q[n+2],Q[n+3]);
    }
}

// ---------------- scan phase B: sequential chunk combine, emit chunk-entry states ----------------
__global__ void scan_phaseB(const float* __restrict__ Pbuf, const float* __restrict__ Qbuf,
                            float* __restrict__ hs)
{
    int idx = blockIdx.x*256 + threadIdx.x;   // over BSZ*DI = 6144
    int b = idx / DI, d = idx % DI;
    float h[16];
    #pragma unroll
    for (int n = 0; n < 16; n++) h[n] = 0.f;
    for (int c = 0; c < NCHUNK; c++) {
        long obase = (((long)c*BSZ + b)*DI + d) * 16;
        #pragma unroll
        for (int n = 0; n < 16; n += 4)
            *(float4*)&hs[obase + n] = make_float4(h[n],h[n+1],h[n+2],h[n+3]);
        long ibase = (((long)b*NCHUNK + c)*DI + d) * 16;
        #pragma unroll
        for (int n = 0; n < 16; n += 4) {
            float4 p = *(const float4*)&Pbuf[ibase + n];
            float4 q = *(const float4*)&Qbuf[ibase + n];
            h[n+0] = p.x*h[n+0] + q.x;
            h[n+1] = p.y*h[n+1] + q.y;
            h[n+2] = p.z*h[n+2] + q.z;
            h[n+3] = p.w*h[n+3] + q.w;
        }
    }
}

// ---------------- scan phase C: replay + y = dot(h,C) + D*x, gated by silu(z) ----------------
// grid: (DI/256, NCHUNK, BSZ)
__global__ void scan_phaseC(const float* __restrict__ delta, const float* __restrict__ xx,
                            const float* __restrict__ dbc,  const float* __restrict__ xz,
                            const float* __restrict__ A_log_l, const float* __restrict__ Dsk_l,
                            const float* __restrict__ hs, float* __restrict__ y)
{
    const int d = blockIdx.x*256 + threadIdx.x;
    const int c = blockIdx.y, b = blockIdx.z;
    __shared__ __align__(16) float sB[CLEN][16];
    __shared__ __align__(16) float sC[CLEN][16];
    const long rbase = (long)b*TLEN + c*CLEN;
    for (int i = threadIdx.x; i < CLEN*32; i += 256) {
        int tt = i >> 5, k = i & 31;
        float v = dbc[(rbase + tt)*80 + 48 + k];
        if (k < 16) sB[tt][k] = v; else sC[tt][k-16] = v;
    }
    __syncthreads();

    float An[16];
    #pragma unroll
    for (int n = 0; n < 16; n++)
        An[n] = -__expf(A_log_l[d*16 + n]) * 1.44269504f;

    float h[16];
    const float* hsp = hs + (((long)c*BSZ + b)*DI + d) * 16;
    #pragma unroll
    for (int n = 0; n < 16; n += 4) {
        float4 v = *(const float4*)&hsp[n];
        h[n] = v.x; h[n+1] = v.y; h[n+2] = v.z; h[n+3] = v.w;
    }
    const float Dv = Dsk_l[d];
    const long off = rbase*DI + d;
    const float* dp = delta + off;
    const float* xp = xx + off;
    const float* zp = xz + rbase*(2L*DI) + DI + d;
    float* yp = y + off;

    for (int tt = 0; tt < CLEN; tt++) {
        float dl  = dp[(long)tt*DI];
        float xv  = xp[(long)tt*DI];
        float dtx = dl * xv;
        float4 b0 = *(const float4*)&sB[tt][0];
        float4 b1 = *(const float4*)&sB[tt][4];
        float4 b2 = *(const float4*)&sB[tt][8];
        float4 b3 = *(const float4*)&sB[tt][12];
        float4 c0 = *(const float4*)&sC[tt][0];
        float4 c1 = *(const float4*)&sC[tt][4];
        float4 c2 = *(const float4*)&sC[tt][8];
        float4 c3 = *(const float4*)&sC[tt][12];
        float bv[16] = {b0.x,b0.y,b0.z,b0.w, b1.x,b1.y,b1.z,b1.w,
                        b2.x,b2.y,b2.z,b2.w, b3.x,b3.y,b3.z,b3.w};
        float cv[16] = {c0.x,c0.y,c0.z,c0.w, c1.x,c1.y,c1.z,c1.w,
                        c2.x,c2.y,c2.z,c2.w, c3.x,c3.y,c3.z,c3.w};
        float yacc = 0.f;
        #pragma unroll
        for (int n = 0; n < 16; n++) {
            float a = ex2f(dl * An[n]);
            h[n] = a*h[n] + dtx*bv[n];
            yacc += h[n]*cv[n];
        }
        float yd = yacc + Dv*xv;
        float zv = zp[(long)tt*(2L*DI)];
        float gate = zv / (1.f + __expf(-zv));   // silu(z)
        yp[(long)tt*DI] = yd * gate;
    }
}

// ---------------- final: rmsnorm + head in one pass ----------------
__global__ void head_k(const float* __restrict__ h, const float* __restrict__ nw,
                       const float* __restrict__ hw, const float* __restrict__ hb,
                       float* __restrict__ out)
{
    int m = blockIdx.x;
    const float* row = h + (long)m*DM;
    float ss = 0.f, dp = 0.f;
    #pragma unroll
    for (int r = 0; r < 3; r++) {
        int i = threadIdx.x + r*256;
        float v = row[i];
        ss += v*v;
        dp += v * nw[i] * hw[i];
    }
    #pragma unroll
    for (int o = 16; o > 0; o >>= 1) {
        ss += __shfl_down_sync(0xffffffffu, ss, o);
        dp += __shfl_down_sync(0xffffffffu, dp, o);
    }
    __shared__ float s_ss[8], s_dp[8];
    if ((threadIdx.x & 31) == 0) { s_ss[threadIdx.x>>5] = ss; s_dp[threadIdx.x>>5] = dp; }
    __syncthreads();
    if (threadIdx.x == 0) {
        float tss = 0.f, tdp = 0.f;
        #pragma unroll
        for (int i = 0; i < 8; i++) { tss += s_ss[i]; tdp += s_dp[i]; }
        out[m] = tdp * rsqrtf(tss * (1.f/DM) + EPSV) + hb[0];
    }
}

// ---------------- launcher ----------------
extern "C" void kernel_launch(void* const* d_in, const int* in_sizes, int n_in,
                              void* d_out, int out_size)
{
    const float* x         = (const float*)d_in[0];
    const float* inp_w     = (const float*)d_in[1];
    const float* inp_b     = (const float*)d_in[2];
    const float* in_proj_w = (const float*)d_in[3];
    const float* conv_w    = (const float*)d_in[4];
    const float* conv_b    = (const float*)d_in[5];
    const float* x_proj_w  = (const float*)d_in[6];
    const float* dt_proj_w = (const float*)d_in[7];
    const float* dt_proj_b = (const float*)d_in[8];
    const float* A_log     = (const float*)d_in[9];
    const float* D_skip    = (const float*)d_in[10];
    const float* out_proj_w= (const float*)d_in[11];
    const float* ln_w      = (const float*)d_in[12];
    const float* norm_w    = (const float*)d_in[13];
    const float* head_w    = (const float*)d_in[14];
    const float* head_b    = (const float*)d_in[15];

    float* buf = nullptr;
    cudaGetSymbolAddress((void**)&buf, g_buf);
    float* h     = buf + OFF_H;
    float* xn    = buf + OFF_XN;
    float* xz    = buf + OFF_XZ;
    float* xx    = buf + OFF_XX;
    float* dbc   = buf + OFF_DBC;
    float* delta = buf + OFF_DELTA;
    float* yb    = buf + OFF_Y;
    float* Pb    = buf + OFF_P;
    float* Qb    = buf + OFF_Q;
    float* hsb   = buf + OFF_HS;

    input_proj_k<<<MROWS, 256>>>(x, inp_w, inp_b, h);

    for (int l = 0; l < NLAYERS; l++) {
        const float* inw  = in_proj_w + (long)l*2*DI*DM;
        const float* cw   = conv_w    + (long)l*DI*4;
        const float* cb   = conv_b    + (long)l*DI;
        const float* xpw  = x_proj_w  + (long)l*80*DI;
        const float* dtw  = dt_proj_w + (long)l*DI*DTR;
        const float* dtb  = dt_proj_b + (long)l*DI;
        const float* Al   = A_log     + (long)l*DI*DS;
        const float* Dsk  = D_skip    + (long)l*DI;
        const float* opw  = out_proj_w+ (long)l*DM*DI;
        const float* lnw  = ln_w      + (long)l*DM;

        rmsnorm_k<<<MROWS, 256>>>(h, lnw, xn);

        // xz[4096,3072] = xn[4096,768] @ inw[3072,768]^T
        sgemm_nt<0><<<dim3((2*DI)/128, MROWS/128), 256>>>(xn, inw, xz, nullptr,
                                                          2*DI, DM, DM, DM, 2*DI);
        conv_silu_k<<<(MROWS*DI)/256, 256>>>(xz, cw, cb, xx);

        // dbc[4096,80] = xx[4096,1536] @ xpw[80,1536]^T
        sgemm_nt<0><<<dim3(1, MROWS/128), 256>>>(xx, xpw, dbc, nullptr,
                                                 80, DI, DI, DI, 80);
        // delta[4096,1536] = softplus(dbc[:, :48] @ dtw[1536,48]^T + dtb)
        sgemm_nt<1><<<dim3(DI/128, MROWS/128), 256>>>(dbc, dtw, delta, dtb,
                                                      DI, DTR, 80, DTR, DI);

        scan_phaseA<<<dim3(DI/256, NCHUNK, BSZ), 256>>>(delta, xx, dbc, Al, Pb, Qb);
        scan_phaseB<<<(BSZ*DI)/256, 256>>>(Pb, Qb, hsb);
        scan_phaseC<<<dim3(DI/256, NCHUNK, BSZ), 256>>>(delta, xx, dbc, xz, Al, Dsk, hsb, yb);

        // h[4096,768] += yb[4096,1536] @ opw[768,1536]^T
        sgemm_nt<2><<<dim3(DM/128, MROWS/128), 256>>>(yb, opw, h, nullptr,
                                                      DM, DI, DI, DI, DM);
    }

    head_k<<<MROWS, 256>>>(h, norm_w, head_w, head_b, (float*)d_out);
}

// round 8
// speedup vs baseline: 1.0028x; 1.0001x over previous
#include <cuda_runtime.h>
#include <math.h>

// ---------------- problem constants ----------------
#define BSZ     4
#define TLEN    1024
#define DM      768
#define DI      1536
#define DS      16
#define DTR     48
#define NLAYERS 4
#define MROWS   (BSZ*TLEN)          // 4096
#define NCHUNK  16
#define CLEN    (TLEN/NCHUNK)       // 64
#define EPSV    1e-5f

// ---------------- scratch (device globals: no cudaMalloc allowed) ----------------
// offsets in floats
#define OFF_H     0L
#define OFF_XN    (OFF_H    + (long)MROWS*DM)          // 3,145,728
#define OFF_XZ    (OFF_XN   + (long)MROWS*DM)
#define OFF_XX    (OFF_XZ   + (long)MROWS*2*DI)
#define OFF_DBC   (OFF_XX   + (long)MROWS*DI)
#define OFF_DELTA (OFF_DBC  + (long)MROWS*80)
#define OFF_Y     (OFF_DELTA+ (long)MROWS*DI)
#define OFF_P     (OFF_Y    + (long)MROWS*DI)
#define OFF_Q     (OFF_P    + (long)BSZ*NCHUNK*DI*DS)
#define OFF_HS    (OFF_Q    + (long)BSZ*NCHUNK*DI*DS)
#define TOTALF    (OFF_HS   + (long)NCHUNK*BSZ*DI*DS)  // 42,795,008 floats (~171 MB)

__device__ float g_buf[TOTALF];

__device__ __forceinline__ float ex2f(float x) {
    float y; asm("ex2.approx.f32 %0, %1;" : "=f"(y) : "f"(x)); return y;
}

// ---------------- input projection: h[m,e] = inp_b[e] + sum_f x[m,f]*inp_w[e,f] ----------------
__global__ void input_proj_k(const float* __restrict__ x, const float* __restrict__ w,
                             const float* __restrict__ b, float* __restrict__ h)
{
    int m = blockIdx.x;
    __shared__ float xs[12];
    if (threadIdx.x < 12) xs[threadIdx.x] = x[m*12 + threadIdx.x];
    __syncthreads();
    for (int e = threadIdx.x; e < DM; e += 256) {
        float acc = b[e];
        const float* wr = w + e*12;
        #pragma unroll
        for (int f = 0; f < 12; f++) acc += xs[f]*wr[f];
        h[(long)m*DM + e] = acc;
    }
}

// ---------------- rmsnorm: out = x * rsqrt(mean(x^2)+eps) * w ----------------
__global__ void rmsnorm_k(const float* __restrict__ x, const float* __restrict__ w,
                          float* __restrict__ out)
{
    int m = blockIdx.x;
    const float* row = x + (long)m*DM;
    float v0 = row[threadIdx.x];
    float v1 = row[threadIdx.x + 256];
    float v2 = row[threadIdx.x + 512];
    float ss = v0*v0 + v1*v1 + v2*v2;
    #pragma unroll
    for (int o = 16; o > 0; o >>= 1) ss += __shfl_down_sync(0xffffffffu, ss, o);
    __shared__ float sred[8];
    __shared__ float s_scale;
    if ((threadIdx.x & 31) == 0) sred[threadIdx.x >> 5] = ss;
    __syncthreads();
    if (threadIdx.x == 0) {
        float tot = 0.f;
        #pragma unroll
        for (int i = 0; i < 8; i++) tot += sred[i];
        s_scale = rsqrtf(tot * (1.f/DM) + EPSV);
    }
    __syncthreads();
    float sc = s_scale;
    float* orow = out + (long)m*DM;
    orow[threadIdx.x]       = v0 * sc * w[threadIdx.x];
    orow[threadIdx.x + 256] = v1 * sc * w[threadIdx.x + 256];
    orow[threadIdx.x + 512] = v2 * sc * w[threadIdx.x + 512];
}

// ---------------- SGEMM NT: C[M,N] = A[M,K] * B[N,K]^T (128x128x8, 8x8 microtile) ----------------
// EPI: 0 = store, 1 = softplus(acc + bias[n]), 2 = C += acc (residual)
template<int EPI>
__global__ __launch_bounds__(256, 2)
void sgemm_nt(const float* __restrict__ A, const float* __restrict__ B,
              float* __restrict__ C, const float* __restrict__ bias,
              int N, int K, int lda, int ldb, int ldc)
{
    __shared__ __align__(16) float As[8][128];
    __shared__ __align__(16) float Bs[8][128];

    const int tid  = threadIdx.x;
    const int bm   = blockIdx.y * 128;
    const int bn   = blockIdx.x * 128;
    const int arow = tid >> 1;
    const int acol = (tid & 1) << 2;
    const int ty   = tid >> 4;
    const int tx   = tid & 15;

    float acc[8][8];
    #pragma unroll
    for (int i = 0; i < 8; i++)
        #pragma unroll
        for (int j = 0; j < 8; j++) acc[i][j] = 0.f;

    const float* Aptr = A + (long)(bm + arow)*lda + acol;
    const float* Bptr = B + (long)(bn + arow)*ldb + acol;
    const bool bvalid = (bn + arow) < N;

    const int nk = K >> 3;
    float4 a_reg = *(const float4*)Aptr;
    float4 b_reg = bvalid ? *(const float4*)Bptr : make_float4(0.f,0.f,0.f,0.f);

    for (int kt = 0; kt < nk; kt++) {
        As[acol+0][arow] = a_reg.x; As[acol+1][arow] = a_reg.y;
        As[acol+2][arow] = a_reg.z; As[acol+3][arow] = a_reg.w;
        Bs[acol+0][arow] = b_reg.x; Bs[acol+1][arow] = b_reg.y;
        Bs[acol+2][arow] = b_reg.z; Bs[acol+3][arow] = b_reg.w;
        __syncthreads();
        if (kt + 1 < nk) {
            a_reg = *(const float4*)(Aptr + (kt+1)*8);
            b_reg = bvalid ? *(const float4*)(Bptr + (kt+1)*8) : make_float4(0.f,0.f,0.f,0.f);
        }
        #pragma unroll
        for (int k = 0; k < 8; k++) {
            float4 a0 = *(const float4*)&As[k][ty*8];
            float4 a1 = *(const float4*)&As[k][ty*8 + 4];
            float4 b0 = *(const float4*)&Bs[k][tx*8];
            float4 b1 = *(const float4*)&Bs[k][tx*8 + 4];
            float av[8] = {a0.x,a0.y,a0.z,a0.w,a1.x,a1.y,a1.z,a1.w};
            float bv[8] = {b0.x,b0.y,b0.z,b0.w,b1.x,b1.y,b1.z,b1.w};
            #pragma unroll
            for (int i = 0; i < 8; i++)
                #pragma unroll
                for (int j = 0; j < 8; j++)
                    acc[i][j] += av[i]*bv[j];
        }
        __syncthreads();
    }

    #pragma unroll
    for (int i = 0; i < 8; i++) {
        long row = bm + ty*8 + i;
        #pragma unroll
        for (int j = 0; j < 8; j++) {
            int col = bn + tx*8 + j;
            if (col < N) {
                float v = acc[i][j];
                if (EPI == 1) {
                    v += bias[col];
                    v = (v > 20.f) ? v : log1pf(__expf(v));   // softplus
                    C[row*ldc + col] = v;
                } else if (EPI == 2) {
                    C[row*ldc + col] += v;
                } else {
                    C[row*ldc + col] = v;
                }
            }
        }
    }
}

// ---------------- depthwise causal conv (k=4) + silu, over xz[:, :DI] ----------------
__global__ void conv_silu_k(const float* __restrict__ xz, const float* __restrict__ cw,
                            const float* __restrict__ cb, float* __restrict__ xx)
{
    long idx = (long)blockIdx.x*256 + threadIdx.x;      // over MROWS*DI
    int d = (int)(idx % DI);
    long bt = idx / DI;
    int t = (int)(bt % TLEN);
    long b = bt / TLEN;
    float acc = cb[d];
    #pragma unroll
    for (int k = 0; k < 4; k++) {
        int ts = t - 3 + k;
        if (ts >= 0) acc += cw[d*4 + k] * xz[(b*TLEN + ts)*(2L*DI) + d];
    }
    float s = acc / (1.f + __expf(-acc));
    xx[idx] = s;
}

// ---------------- selective scan, phase A: per-chunk (P, Q) composition ----------------
// grid: (DI/256, NCHUNK, BSZ)
__global__ void scan_phaseA(const float* __restrict__ delta, const float* __restrict__ xx,
                            const float* __restrict__ dbc,  const float* __restrict__ A_log_l,
                            float* __restrict__ Pbuf, float* __restrict__ Qbuf)
{
    const int d = blockIdx.x*256 + threadIdx.x;
    const int c = blockIdx.y, b = blockIdx.z;
    __shared__ __align__(16) float sB[CLEN][16];
    const long rbase = (long)b*TLEN + c*CLEN;
    for (int i = threadIdx.x; i < CLEN*16; i += 256) {
        int tt = i >> 4, n = i & 15;
        sB[tt][n] = dbc[(rbase + tt)*80 + 48 + n];
    }
    __syncthreads();

    float An[16];
    #pragma unroll
    for (int n = 0; n < 16; n++)
        An[n] = -__expf(A_log_l[d*16 + n]) * 1.44269504f;   // A * log2(e)

    float P[16], Q[16];
    #pragma unroll
    for (int n = 0; n < 16; n++) { P[n] = 1.f; Q[n] = 0.f; }

    const long off = rbase*DI + d;
    const float* dp = delta + off;
    const float* xp = xx + off;

    for (int tt = 0; tt < CLEN; tt++) {
        float dl  = dp[(long)tt*DI];
        float xv  = xp[(long)tt*DI];
        float dtx = dl * xv;
        float4 b0 = *(const float4*)&sB[tt][0];
        float4 b1 = *(const float4*)&sB[tt][4];
        float4 b2 = *(const float4*)&sB[tt][8];
        float4 b3 = *(const float4*)&sB[tt][12];
        float bv[16] = {b0.x,b0.y,b0.z,b0.w, b1.x,b1.y,b1.z,b1.w,
                        b2.x,b2.y,b2.z,b2.w, b3.x,b3.y,b3.z,b3.w};
        #pragma unroll
        for (int n = 0; n < 16; n++) {
            float a = ex2f(dl * An[n]);
            P[n] *= a;
            Q[n] = a*Q[n] + dtx*bv[n];
        }
    }
    long base = (((long)b*NCHUNK + c)*DI + d) * 16;
    #pragma unroll
    for (int n = 0; n < 16; n += 4) {
        *(float4*)&Pbuf[base + n] = make_float4(P[n],P[n+1],P[n+2],P[n+3]);
        *(float4*)&Qbuf[base + n] = make_float4(Q[n],Q[n+1],Q[n+2],Q[n+3]);
    }
}

// ---------------- scan phase B: sequential chunk combine, emit chunk-entry states ----------------
__global__ void scan_phaseB(const float* __restrict__ Pbuf, const float* __restrict__ Qbuf,
                            float* __restrict__ hs)
{
    int idx = blockIdx.x*256 + threadIdx.x;   // over BSZ*DI = 6144
    int b = idx / DI, d = idx % DI;
    float h[16];
    #pragma unroll
    for (int n = 0; n < 16; n++) h[n] = 0.f;
    for (int c = 0; c < NCHUNK; c++) {
        long obase = (((long)c*BSZ + b)*DI + d) * 16;
        #pragma unroll
        for (int n = 0; n < 16; n += 4)
            *(float4*)&hs[obase + n] = make_float4(h[n],h[n+1],h[n+2],h[n+3]);
        long ibase = (((long)b*NCHUNK + c)*DI + d) * 16;
        #pragma unroll
        for (int n = 0; n < 16; n += 4) {
            float4 p = *(const float4*)&Pbuf[ibase + n];
            float4 q = *(const float4*)&Qbuf[ibase + n];
            h[n+0] = p.x*h[n+0] + q.x;
            h[n+1] = p.y*h[n+1] + q.y;
            h[n+2] = p.z*h[n+2] + q.z;
            h[n+3] = p.w*h[n+3] + q.w;
        }
    }
}

// ---------------- scan phase C: replay + y = dot(h,C) + D*x, gated by silu(z) ----------------
// grid: (DI/256, NCHUNK, BSZ)
__global__ void scan_phaseC(const float* __restrict__ delta, const float* __restrict__ xx,
                            const float* __restrict__ dbc,  const float* __restrict__ xz,
                            const float* __restrict__ A_log_l, const float* __restrict__ Dsk_l,
                            const float* __restrict__ hs, float* __restrict__ y)
{
    const int d = blockIdx.x*256 + threadIdx.x;
    const int c = blockIdx.y, b = blockIdx.z;
    __shared__ __align__(16) float sB[CLEN][16];
    __shared__ __align__(16) float sC[CLEN][16];
    const long rbase = (long)b*TLEN + c*CLEN;
    for (int i = threadIdx.x; i < CLEN*32; i += 256) {
        int tt = i >> 5, k = i & 31;
        float v = dbc[(rbase + tt)*80 + 48 + k];
        if (k < 16) sB[tt][k] = v; else sC[tt][k-16] = v;
    }
    __syncthreads();

    float An[16];
    #pragma unroll
    for (int n = 0; n < 16; n++)
        An[n] = -__expf(A_log_l[d*16 + n]) * 1.44269504f;

    float h[16];
    const float* hsp = hs + (((long)c*BSZ + b)*DI + d) * 16;
    #pragma unroll
    for (int n = 0; n < 16; n += 4) {
        float4 v = *(const float4*)&hsp[n];
        h[n] = v.x; h[n+1] = v.y; h[n+2] = v.z; h[n+3] = v.w;
    }
    const float Dv = Dsk_l[d];
    const long off = rbase*DI + d;
    const float* dp = delta + off;
    const float* xp = xx + off;
    const float* zp = xz + rbase*(2L*DI) + DI + d;
    float* yp = y + off;

    for (int tt = 0; tt < CLEN; tt++) {
        float dl  = dp[(long)tt*DI];
        float xv  = xp[(long)tt*DI];
        float dtx = dl * xv;
        float4 b0 = *(const float4*)&sB[tt][0];
        float4 b1 = *(const float4*)&sB[tt][4];
        float4 b2 = *(const float4*)&sB[tt][8];
        float4 b3 = *(const float4*)&sB[tt][12];
        float4 c0 = *(const float4*)&sC[tt][0];
        float4 c1 = *(const float4*)&sC[tt][4];
        float4 c2 = *(const float4*)&sC[tt][8];
        float4 c3 = *(const float4*)&sC[tt][12];
        float bv[16] = {b0.x,b0.y,b0.z,b0.w, b1.x,b1.y,b1.z,b1.w,
                        b2.x,b2.y,b2.z,b2.w, b3.x,b3.y,b3.z,b3.w};
        float cv[16] = {c0.x,c0.y,c0.z,c0.w, c1.x,c1.y,c1.z,c1.w,
                        c2.x,c2.y,c2.z,c2.w, c3.x,c3.y,c3.z,c3.w};
        float yacc = 0.f;
        #pragma unroll
        for (int n = 0; n < 16; n++) {
            float a = ex2f(dl * An[n]);
            h[n] = a*h[n] + dtx*bv[n];
            yacc += h[n]*cv[n];
        }
        float yd = yacc + Dv*xv;
        float zv = zp[(long)tt*(2L*DI)];
        float gate = zv / (1.f + __expf(-zv));   // silu(z)
        yp[(long)tt*DI] = yd * gate;
    }
}

// ---------------- final: rmsnorm + head in one pass ----------------
__global__ void head_k(const float* __restrict__ h, const float* __restrict__ nw,
                       const float* __restrict__ hw, const float* __restrict__ hb,
                       float* __restrict__ out)
{
    int m = blockIdx.x;
    const float* row = h + (long)m*DM;
    float ss = 0.f, dp = 0.f;
    #pragma unroll
    for (int r = 0; r < 3; r++) {
        int i = threadIdx.x + r*256;
        float v = row[i];
        ss += v*v;
        dp += v * nw[i] * hw[i];
    }
    #pragma unroll
    for (int o = 16; o > 0; o >>= 1) {
        ss += __shfl_down_sync(0xffffffffu, ss, o);
        dp += __shfl_down_sync(0xffffffffu, dp, o);
    }
    __shared__ float s_ss[8], s_dp[8];
    if ((threadIdx.x & 31) == 0) { s_ss[threadIdx.x>>5] = ss; s_dp[threadIdx.x>>5] = dp; }
    __syncthreads();
    if (threadIdx.x == 0) {
        float tss = 0.f, tdp = 0.f;
        #pragma unroll
        for (int i = 0; i < 8; i++) { tss += s_ss[i]; tdp += s_dp[i]; }
        out[m] = tdp * rsqrtf(tss * (1.f/DM) + EPSV) + hb[0];
    }
}

// ---------------- launcher ----------------
extern "C" void kernel_launch(void* const* d_in, const int* in_sizes, int n_in,
                              void* d_out, int out_size)
{
    const float* x         = (const float*)d_in[0];
    const float* inp_w     = (const float*)d_in[1];
    const float* inp_b     = (const float*)d_in[2];
    const float* in_proj_w = (const float*)d_in[3];
    const float* conv_w    = (const float*)d_in[4];
    const float* conv_b    = (const float*)d_in[5];
    const float* x_proj_w  = (const float*)d_in[6];
    const float* dt_proj_w = (const float*)d_in[7];
    const float* dt_proj_b = (const float*)d_in[8];
    const float* A_log     = (const float*)d_in[9];
    const float* D_skip    = (const float*)d_in[10];
    const float* out_proj_w= (const float*)d_in[11];
    const float* ln_w      = (const float*)d_in[12];
    const float* norm_w    = (const float*)d_in[13];
    const float* head_w    = (const float*)d_in[14];
    const float* head_b    = (const float*)d_in[15];

    float* buf = nullptr;
    cudaGetSymbolAddress((void**)&buf, g_buf);
    float* h     = buf + OFF_H;
    float* xn    = buf + OFF_XN;
    float* xz    = buf + OFF_XZ;
    float* xx    = buf + OFF_XX;
    float* dbc   = buf + OFF_DBC;
    float* delta = buf + OFF_DELTA;
    float* yb    = buf + OFF_Y;
    float* Pb    = buf + OFF_P;
    float* Qb    = buf + OFF_Q;
    float* hsb   = buf + OFF_HS;

    input_proj_k<<<MROWS, 256>>>(x, inp_w, inp_b, h);

    for (int l = 0; l < NLAYERS; l++) {
        const float* inw  = in_proj_w + (long)l*2*DI*DM;
        const float* cw   = conv_w    + (long)l*DI*4;
        const float* cb   = conv_b    + (long)l*DI;
        const float* xpw  = x_proj_w  + (long)l*80*DI;
        const float* dtw  = dt_proj_w + (long)l*DI*DTR;
        const float* dtb  = dt_proj_b + (long)l*DI;
        const float* Al   = A_log     + (long)l*DI*DS;
        const float* Dsk  = D_skip    + (long)l*DI;
        const float* opw  = out_proj_w+ (long)l*DM*DI;
        const float* lnw  = ln_w      + (long)l*DM;

        rmsnorm_k<<<MROWS, 256>>>(h, lnw, xn);

        // xz[4096,3072] = xn[4096,768] @ inw[3072,768]^T
        sgemm_nt<0><<<dim3((2*DI)/128, MROWS/128), 256>>>(xn, inw, xz, nullptr,
                                                          2*DI, DM, DM, DM, 2*DI);
        conv_silu_k<<<(MROWS*DI)/256, 256>>>(xz, cw, cb, xx);

        // dbc[4096,80] = xx[4096,1536] @ xpw[80,1536]^T
        sgemm_nt<0><<<dim3(1, MROWS/128), 256>>>(xx, xpw, dbc, nullptr,
                                                 80, DI, DI, DI, 80);
        // delta[4096,1536] = softplus(dbc[:, :48] @ dtw[1536,48]^T + dtb)
        sgemm_nt<1><<<dim3(DI/128, MROWS/128), 256>>>(dbc, dtw, delta, dtb,
                                                      DI, DTR, 80, DTR, DI);

        scan_phaseA<<<dim3(DI/256, NCHUNK, BSZ), 256>>>(delta, xx, dbc, Al, Pb, Qb);
        scan_phaseB<<<(BSZ*DI)/256, 256>>>(Pb, Qb, hsb);
        scan_phaseC<<<dim3(DI/256, NCHUNK, BSZ), 256>>>(delta, xx, dbc, xz, Al, Dsk, hsb, yb);

        // h[4096,768] += yb[4096,1536] @ opw[768,1536]^T
        sgemm_nt<2><<<dim3(DM/128, MROWS/128), 256>>>(yb, opw, h, nullptr,
                                                      DM, DI, DI, DI, DM);
    }

    head_k<<<MROWS, 256>>>(h, norm_w, head_w, head_b, (float*)d_out);
}

// round 9
// speedup vs baseline: 1.0033x; 1.0006x over previous
#include <cuda_runtime.h>
#include <math.h>

// ---------------- problem constants ----------------
#define BSZ     4
#define TLEN    1024
#define DM      768
#define DI      1536
#define DS      16
#define DTR     48
#define NLAYERS 4
#define MROWS   (BSZ*TLEN)          // 4096
#define NCHUNK  16
#define CLEN    (TLEN/NCHUNK)       // 64
#define EPSV    1e-5f

// ---------------- scratch (device globals: no cudaMalloc allowed) ----------------
// offsets in floats
#define OFF_H     0L
#define OFF_XN    (OFF_H    + (long)MROWS*DM)          // 3,145,728
#define OFF_XZ    (OFF_XN   + (long)MROWS*DM)
#define OFF_XX    (OFF_XZ   + (long)MROWS*2*DI)
#define OFF_DBC   (OFF_XX   + (long)MROWS*DI)
#define OFF_DELTA (OFF_DBC  + (long)MROWS*80)
#define OFF_Y     (OFF_DELTA+ (long)MROWS*DI)
#define OFF_P     (OFF_Y    + (long)MROWS*DI)
#define OFF_Q     (OFF_P    + (long)BSZ*NCHUNK*DI*DS)
#define OFF_HS    (OFF_Q    + (long)BSZ*NCHUNK*DI*DS)
#define TOTALF    (OFF_HS   + (long)NCHUNK*BSZ*DI*DS)  // 42,795,008 floats (~171 MB)

__device__ float g_buf[TOTALF];

__device__ __forceinline__ float ex2f(float x) {
    float y; asm("ex2.approx.f32 %0, %1;" : "=f"(y) : "f"(x)); return y;
}

// ---------------- input projection: h[m,e] = inp_b[e] + sum_f x[m,f]*inp_w[e,f] ----------------
__global__ void input_proj_k(const float* __restrict__ x, const float* __restrict__ w,
                             const float* __restrict__ b, float* __restrict__ h)
{
    int m = blockIdx.x;
    __shared__ float xs[12];
    if (threadIdx.x < 12) xs[threadIdx.x] = x[m*12 + threadIdx.x];
    __syncthreads();
    for (int e = threadIdx.x; e < DM; e += 256) {
        float acc = b[e];
        const float* wr = w + e*12;
        #pragma unroll
        for (int f = 0; f < 12; f++) acc += xs[f]*wr[f];
        h[(long)m*DM + e] = acc;
    }
}

// ---------------- rmsnorm: out = x * rsqrt(mean(x^2)+eps) * w ----------------
__global__ void rmsnorm_k(const float* __restrict__ x, const float* __restrict__ w,
                          float* __restrict__ out)
{
    int m = blockIdx.x;
    const float* row = x + (long)m*DM;
    float v0 = row[threadIdx.x];
    float v1 = row[threadIdx.x + 256];
    float v2 = row[threadIdx.x + 512];
    float ss = v0*v0 + v1*v1 + v2*v2;
    #pragma unroll
    for (int o = 16; o > 0; o >>= 1) ss += __shfl_down_sync(0xffffffffu, ss, o);
    __shared__ float sred[8];
    __shared__ float s_scale;
    if ((threadIdx.x & 31) == 0) sred[threadIdx.x >> 5] = ss;
    __syncthreads();
    if (threadIdx.x == 0) {
        float tot = 0.f;
        #pragma unroll
        for (int i = 0; i < 8; i++) tot += sred[i];
        s_scale = rsqrtf(tot * (1.f/DM) + EPSV);
    }
    __syncthreads();
    float sc = s_scale;
    float* orow = out + (long)m*DM;
    orow[threadIdx.x]       = v0 * sc * w[threadIdx.x];
    orow[threadIdx.x + 256] = v1 * sc * w[threadIdx.x + 256];
    orow[threadIdx.x + 512] = v2 * sc * w[threadIdx.x + 512];
}

// ---------------- SGEMM NT: C[M,N] = A[M,K] * B[N,K]^T (128x128x8, 8x8 microtile) ----------------
// EPI: 0 = store, 1 = softplus(acc + bias[n]), 2 = C += acc (residual)
template<int EPI>
__global__ __launch_bounds__(256, 2)
void sgemm_nt(const float* __restrict__ A, const float* __restrict__ B,
              float* __restrict__ C, const float* __restrict__ bias,
              int N, int K, int lda, int ldb, int ldc)
{
    __shared__ __align__(16) float As[8][128];
    __shared__ __align__(16) float Bs[8][128];

    const int tid  = threadIdx.x;
    const int bm   = blockIdx.y * 128;
    const int bn   = blockIdx.x * 128;
    const int arow = tid >> 1;
    const int acol = (tid & 1) << 2;
    const int ty   = tid >> 4;
    const int tx   = tid & 15;

    float acc[8][8];
    #pragma unroll
    for (int i = 0; i < 8; i++)
        #pragma unroll
        for (int j = 0; j < 8; j++) acc[i][j] = 0.f;

    const float* Aptr = A + (long)(bm + arow)*lda + acol;
    const float* Bptr = B + (long)(bn + arow)*ldb + acol;
    const bool bvalid = (bn + arow) < N;

    const int nk = K >> 3;
    float4 a_reg = *(const float4*)Aptr;
    float4 b_reg = bvalid ? *(const float4*)Bptr : make_float4(0.f,0.f,0.f,0.f);

    for (int kt = 0; kt < nk; kt++) {
        As[acol+0][arow] = a_reg.x; As[acol+1][arow] = a_reg.y;
        As[acol+2][arow] = a_reg.z; As[acol+3][arow] = a_reg.w;
        Bs[acol+0][arow] = b_reg.x; Bs[acol+1][arow] = b_reg.y;
        Bs[acol+2][arow] = b_reg.z; Bs[acol+3][arow] = b_reg.w;
        __syncthreads();
        if (kt + 1 < nk) {
            a_reg = *(const float4*)(Aptr + (kt+1)*8);
            b_reg = bvalid ? *(const float4*)(Bptr + (kt+1)*8) : make_float4(0.f,0.f,0.f,0.f);
        }
        #pragma unroll
        for (int k = 0; k < 8; k++) {
            float4 a0 = *(const float4*)&As[k][ty*8];
            float4 a1 = *(const float4*)&As[k][ty*8 + 4];
            float4 b0 = *(const float4*)&Bs[k][tx*8];
            float4 b1 = *(const float4*)&Bs[k][tx*8 + 4];
            float av[8] = {a0.x,a0.y,a0.z,a0.w,a1.x,a1.y,a1.z,a1.w};
            float bv[8] = {b0.x,b0.y,b0.z,b0.w,b1.x,b1.y,b1.z,b1.w};
            #pragma unroll
            for (int i = 0; i < 8; i++)
                #pragma unroll
                for (int j = 0; j < 8; j++)
                    acc[i][j] += av[i]*bv[j];
        }
        __syncthreads();
    }

    #pragma unroll
    for (int i = 0; i < 8; i++) {
        long row = bm + ty*8 + i;
        #pragma unroll
        for (int j = 0; j < 8; j++) {
            int col = bn + tx*8 + j;
            if (col < N) {
                float v = acc[i][j];
                if (EPI == 1) {
                    v += bias[col];
                    v = (v > 20.f) ? v : log1pf(__expf(v));   // softplus
                    C[row*ldc + col] = v;
                } else if (EPI == 2) {
                    C[row*ldc + col] += v;
                } else {
                    C[row*ldc + col] = v;
                }
            }
        }
    }
}

// ---------------- depthwise causal conv (k=4) + silu, over xz[:, :DI] ----------------
__global__ void conv_silu_k(const float* __restrict__ xz, const float* __restrict__ cw,
                            const float* __restrict__ cb, float* __restrict__ xx)
{
    long idx = (long)blockIdx.x*256 + threadIdx.x;      // over MROWS*DI
    int d = (int)(idx % DI);
    long bt = idx / DI;
    int t = (int)(bt % TLEN);
    long b = bt / TLEN;
    float acc = cb[d];
    #pragma unroll
    for (int k = 0; k < 4; k++) {
        int ts = t - 3 + k;
        if (ts >= 0) acc += cw[d*4 + k] * xz[(b*TLEN + ts)*(2L*DI) + d];
    }
    float s = acc / (1.f + __expf(-acc));
    xx[idx] = s;
}

// ---------------- selective scan, phase A: per-chunk (P, Q) composition ----------------
// grid: (DI/256, NCHUNK, BSZ)
__global__ void scan_phaseA(const float* __restrict__ delta, const float* __restrict__ xx,
                            const float* __restrict__ dbc,  const float* __restrict__ A_log_l,
                            float* __restrict__ Pbuf, float* __restrict__ Qbuf)
{
    const int d = blockIdx.x*256 + threadIdx.x;
    const int c = blockIdx.y, b = blockIdx.z;
    __shared__ __align__(16) float sB[CLEN][16];
    const long rbase = (long)b*TLEN + c*CLEN;
    for (int i = threadIdx.x; i < CLEN*16; i += 256) {
        int tt = i >> 4, n = i & 15;
        sB[tt][n] = dbc[(rbase + tt)*80 + 48 + n];
    }
    __syncthreads();

    float An[16];
    #pragma unroll
    for (int n = 0; n < 16; n++)
        An[n] = -__expf(A_log_l[d*16 + n]) * 1.44269504f;   // A * log2(e)

    float P[16], Q[16];
    #pragma unroll
    for (int n = 0; n < 16; n++) { P[n] = 1.f; Q[n] = 0.f; }

    const long off = rbase*DI + d;
    const float* dp = delta + off;
    const float* xp = xx + off;

    for (int tt = 0; tt < CLEN; tt++) {
        float dl  = dp[(long)tt*DI];
        float xv  = xp[(long)tt*DI];
        float dtx = dl * xv;
        float4 b0 = *(const float4*)&sB[tt][0];
        float4 b1 = *(const float4*)&sB[tt][4];
        float4 b2 = *(const float4*)&sB[tt][8];
        float4 b3 = *(const float4*)&sB[tt][12];
        float bv[16] = {b0.x,b0.y,b0.z,b0.w, b1.x,b1.y,b1.z,b1.w,
                        b2.x,b2.y,b2.z,b2.w, b3.x,b3.y,b3.z,b3.w};
        #pragma unroll
        for (int n = 0; n < 16; n++) {
            float a = ex2f(dl * An[n]);
            P[n] *= a;
            Q[n] = a*Q[n] + dtx*bv[n];
        }
    }
    long base = (((long)b*NCHUNK + c)*DI + d) * 16;
    #pragma unroll
    for (int n = 0; n < 16; n += 4) {
        *(float4*)&Pbuf[base + n] = make_float4(P[n],P[n+1],P[n+2],P[n+3]);
        *(float4*)&Qbuf[base + n] = make_float4(Q[n],Q[n+1],Q[n+2],Q[n+3]);
    }
}

// ---------------- scan phase B: sequential chunk combine, emit chunk-entry states ----------------
__global__ void scan_phaseB(const float* __restrict__ Pbuf, const float* __restrict__ Qbuf,
                            float* __restrict__ hs)
{
    int idx = blockIdx.x*256 + threadIdx.x;   // over BSZ*DI = 6144
    int b = idx / DI, d = idx % DI;
    float h[16];
    #pragma unroll
    for (int n = 0; n < 16; n++) h[n] = 0.f;
    for (int c = 0; c < NCHUNK; c++) {
        long obase = (((long)c*BSZ + b)*DI + d) * 16;
        #pragma unroll
        for (int n = 0; n < 16; n += 4)
            *(float4*)&hs[obase + n] = make_float4(h[n],h[n+1],h[n+2],h[n+3]);
        long ibase = (((long)b*NCHUNK + c)*DI + d) * 16;
        #pragma unroll
        for (int n = 0; n < 16; n += 4) {
            float4 p = *(const float4*)&Pbuf[ibase + n];
            float4 q = *(const float4*)&Qbuf[ibase + n];
            h[n+0] = p.x*h[n+0] + q.x;
            h[n+1] = p.y*h[n+1] + q.y;
            h[n+2] = p.z*h[n+2] + q.z;
            h[n+3] = p.w*h[n+3] + q.w;
        }
    }
}

// ---------------- scan phase C: replay + y = dot(h,C) + D*x, gated by silu(z) ----------------
// grid: (DI/256, NCHUNK, BSZ)
__global__ void scan_phaseC(const float* __restrict__ delta, const float* __restrict__ xx,
                            const float* __restrict__ dbc,  const float* __restrict__ xz,
                            const float* __restrict__ A_log_l, const float* __restrict__ Dsk_l,
                            const float* __restrict__ hs, float* __restrict__ y)
{
    const int d = blockIdx.x*256 + threadIdx.x;
    const int c = blockIdx.y, b = blockIdx.z;
    __shared__ __align__(16) float sB[CLEN][16];
    __shared__ __align__(16) float sC[CLEN][16];
    const long rbase = (long)b*TLEN + c*CLEN;
    for (int i = threadIdx.x; i < CLEN*32; i += 256) {
        int tt = i >> 5, k = i & 31;
        float v = dbc[(rbase + tt)*80 + 48 + k];
        if (k < 16) sB[tt][k] = v; else sC[tt][k-16] = v;
    }
    __syncthreads();

    float An[16];
    #pragma unroll
    for (int n = 0; n < 16; n++)
        An[n] = -__expf(A_log_l[d*16 + n]) * 1.44269504f;

    float h[16];
    const float* hsp = hs + (((long)c*BSZ + b)*DI + d) * 16;
    #pragma unroll
    for (int n = 0; n < 16; n += 4) {
        float4 v = *(const float4*)&hsp[n];
        h[n] = v.x; h[n+1] = v.y; h[n+2] = v.z; h[n+3] = v.w;
    }
    const float Dv = Dsk_l[d];
    const long off = rbase*DI + d;
    const float* dp = delta + off;
    const float* xp = xx + off;
    const float* zp = xz + rbase*(2L*DI) + DI + d;
    float* yp = y + off;

    for (int tt = 0; tt < CLEN; tt++) {
        float dl  = dp[(long)tt*DI];
        float xv  = xp[(long)tt*DI];
        float dtx = dl * xv;
        float4 b0 = *(const float4*)&sB[tt][0];
        float4 b1 = *(const float4*)&sB[tt][4];
        float4 b2 = *(const float4*)&sB[tt][8];
        float4 b3 = *(const float4*)&sB[tt][12];
        float4 c0 = *(const float4*)&sC[tt][0];
        float4 c1 = *(const float4*)&sC[tt][4];
        float4 c2 = *(const float4*)&sC[tt][8];
        float4 c3 = *(const float4*)&sC[tt][12];
        float bv[16] = {b0.x,b0.y,b0.z,b0.w, b1.x,b1.y,b1.z,b1.w,
                        b2.x,b2.y,b2.z,b2.w, b3.x,b3.y,b3.z,b3.w};
        float cv[16] = {c0.x,c0.y,c0.z,c0.w, c1.x,c1.y,c1.z,c1.w,
                        c2.x,c2.y,c2.z,c2.w, c3.x,c3.y,c3.z,c3.w};
        float yacc = 0.f;
        #pragma unroll
        for (int n = 0; n < 16; n++) {
            float a = ex2f(dl * An[n]);
            h[n] = a*h[n] + dtx*bv[n];
            yacc += h[n]*cv[n];
        }
        float yd = yacc + Dv*xv;
        float zv = zp[(long)tt*(2L*DI)];
        float gate = zv / (1.f + __expf(-zv));   // silu(z)
        yp[(long)tt*DI] = yd * gate;
    }
}

// ---------------- final: rmsnorm + head in one pass ----------------
__global__ void head_k(const float* __restrict__ h, const float* __restrict__ nw,
                       const float* __restrict__ hw, const float* __restrict__ hb,
                       float* __restrict__ out)
{
    int m = blockIdx.x;
    const float* row = h + (long)m*DM;
    float ss = 0.f, dp = 0.f;
    #pragma unroll
    for (int r = 0; r < 3; r++) {
        int i = threadIdx.x + r*256;
        float v = row[i];
        ss += v*v;
        dp += v * nw[i] * hw[i];
    }
    #pragma unroll
    for (int o = 16; o > 0; o >>= 1) {
        ss += __shfl_down_sync(0xffffffffu, ss, o);
        dp += __shfl_down_sync(0xffffffffu, dp, o);
    }
    __shared__ float s_ss[8], s_dp[8];
    if ((threadIdx.x & 31) == 0) { s_ss[threadIdx.x>>5] = ss; s_dp[threadIdx.x>>5] = dp; }
    __syncthreads();
    if (threadIdx.x == 0) {
        float tss = 0.f, tdp = 0.f;
        #pragma unroll
        for (int i = 0; i < 8; i++) { tss += s_ss[i]; tdp += s_dp[i]; }
        out[m] = tdp * rsqrtf(tss * (1.f/DM) + EPSV) + hb[0];
    }
}

// ---------------- launcher ----------------
extern "C" void kernel_launch(void* const* d_in, const int* in_sizes, int n_in,
                              void* d_out, int out_size)
{
    const float* x         = (const float*)d_in[0];
    const float* inp_w     = (const float*)d_in[1];
    const float* inp_b     = (const float*)d_in[2];
    const float* in_proj_w = (const float*)d_in[3];
    const float* conv_w    = (const float*)d_in[4];
    const float* conv_b    = (const float*)d_in[5];
    const float* x_proj_w  = (const float*)d_in[6];
    const float* dt_proj_w = (const float*)d_in[7];
    const float* dt_proj_b = (const float*)d_in[8];
    const float* A_log     = (const float*)d_in[9];
    const float* D_skip    = (const float*)d_in[10];
    const float* out_proj_w= (const float*)d_in[11];
    const float* ln_w      = (const float*)d_in[12];
    const float* norm_w    = (const float*)d_in[13];
    const float* head_w    = (const float*)d_in[14];
    const float* head_b    = (const float*)d_in[15];

    float* buf = nullptr;
    cudaGetSymbolAddress((void**)&buf, g_buf);
    float* h     = buf + OFF_H;
    float* xn    = buf + OFF_XN;
    float* xz    = buf + OFF_XZ;
    float* xx    = buf + OFF_XX;
    float* dbc   = buf + OFF_DBC;
    float* delta = buf + OFF_DELTA;
    float* yb    = buf + OFF_Y;
    float* Pb    = buf + OFF_P;
    float* Qb    = buf + OFF_Q;
    float* hsb   = buf + OFF_HS;

    input_proj_k<<<MROWS, 256>>>(x, inp_w, inp_b, h);

    for (int l = 0; l < NLAYERS; l++) {
        const float* inw  = in_proj_w + (long)l*2*DI*DM;
        const float* cw   = conv_w    + (long)l*DI*4;
        const float* cb   = conv_b    + (long)l*DI;
        const float* xpw  = x_proj_w  + (long)l*80*DI;
        const float* dtw  = dt_proj_w + (long)l*DI*DTR;
        const float* dtb  = dt_proj_b + (long)l*DI;
        const float* Al   = A_log     + (long)l*DI*DS;
        const float* Dsk  = D_skip    + (long)l*DI;
        const float* opw  = out_proj_w+ (long)l*DM*DI;
        const float* lnw  = ln_w      + (long)l*DM;

        rmsnorm_k<<<MROWS, 256>>>(h, lnw, xn);

        // xz[4096,3072] = xn[4096,768] @ inw[3072,768]^T
        sgemm_nt<0><<<dim3((2*DI)/128, MROWS/128), 256>>>(xn, inw, xz, nullptr,
                                                          2*DI, DM, DM, DM, 2*DI);
        conv_silu_k<<<(MROWS*DI)/256, 256>>>(xz, cw, cb, xx);

        // dbc[4096,80] = xx[4096,1536] @ xpw[80,1536]^T
        sgemm_nt<0><<<dim3(1, MROWS/128), 256>>>(xx, xpw, dbc, nullptr,
                                                 80, DI, DI, DI, 80);
        // delta[4096,1536] = softplus(dbc[:, :48] @ dtw[1536,48]^T + dtb)
        sgemm_nt<1><<<dim3(DI/128, MROWS/128), 256>>>(dbc, dtw, delta, dtb,
                                                      DI, DTR, 80, DTR, DI);

        scan_phaseA<<<dim3(DI/256, NCHUNK, BSZ), 256>>>(delta, xx, dbc, Al, Pb, Qb);
        scan_phaseB<<<(BSZ*DI)/256, 256>>>(Pb, Qb, hsb);
        scan_phaseC<<<dim3(DI/256, NCHUNK, BSZ), 256>>>(delta, xx, dbc, xz, Al, Dsk, hsb, yb);

        // h[4096,768] += yb[4096,1536] @ opw[768,1536]^T
        sgemm_nt<2><<<dim3(DM/128, MROWS/128), 256>>>(yb, opw, h, nullptr,
                                                      DM, DI, DI, DI, DM);
    }

    head_k<<<MROWS, 256>>>(h, norm_w, head_w, head_b, (float*)d_out);
}

// round 10
// speedup vs baseline: 1.0041x; 1.0008x over previous
#include <cuda_runtime.h>
#include <math.h>

// ---------------- problem constants ----------------
#define BSZ     4
#define TLEN    1024
#define DM      768
#define DI      1536
#define DS      16
#define DTR     48
#define NLAYERS 4
#define MROWS   (BSZ*TLEN)          // 4096
#define NCHUNK  16
#define CLEN    (TLEN/NCHUNK)       // 64
#define EPSV    1e-5f

// ---------------- scratch (device globals: no cudaMalloc allowed) ----------------
// offsets in floats
#define OFF_H     0L
#define OFF_XN    (OFF_H    + (long)MROWS*DM)          // 3,145,728
#define OFF_XZ    (OFF_XN   + (long)MROWS*DM)
#define OFF_XX    (OFF_XZ   + (long)MROWS*2*DI)
#define OFF_DBC   (OFF_XX   + (long)MROWS*DI)
#define OFF_DELTA (OFF_DBC  + (long)MROWS*80)
#define OFF_Y     (OFF_DELTA+ (long)MROWS*DI)
#define OFF_P     (OFF_Y    + (long)MROWS*DI)
#define OFF_Q     (OFF_P    + (long)BSZ*NCHUNK*DI*DS)
#define OFF_HS    (OFF_Q    + (long)BSZ*NCHUNK*DI*DS)
#define TOTALF    (OFF_HS   + (long)NCHUNK*BSZ*DI*DS)  // 42,795,008 floats (~171 MB)

__device__ float g_buf[TOTALF];

__device__ __forceinline__ float ex2f(float x) {
    float y; asm("ex2.approx.f32 %0, %1;" : "=f"(y) : "f"(x)); return y;
}

// ---------------- input projection: h[m,e] = inp_b[e] + sum_f x[m,f]*inp_w[e,f] ----------------
__global__ void input_proj_k(const float* __restrict__ x, const float* __restrict__ w,
                             const float* __restrict__ b, float* __restrict__ h)
{
    int m = blockIdx.x;
    __shared__ float xs[12];
    if (threadIdx.x < 12) xs[threadIdx.x] = x[m*12 + threadIdx.x];
    __syncthreads();
    for (int e = threadIdx.x; e < DM; e += 256) {
        float acc = b[e];
        const float* wr = w + e*12;
        #pragma unroll
        for (int f = 0; f < 12; f++) acc += xs[f]*wr[f];
        h[(long)m*DM + e] = acc;
    }
}

// ---------------- rmsnorm: out = x * rsqrt(mean(x^2)+eps) * w ----------------
__global__ void rmsnorm_k(const float* __restrict__ x, const float* __restrict__ w,
                          float* __restrict__ out)
{
    int m = blockIdx.x;
    const float* row = x + (long)m*DM;
    float v0 = row[threadIdx.x];
    float v1 = row[threadIdx.x + 256];
    float v2 = row[threadIdx.x + 512];
    float ss = v0*v0 + v1*v1 + v2*v2;
    #pragma unroll
    for (int o = 16; o > 0; o >>= 1) ss += __shfl_down_sync(0xffffffffu, ss, o);
    __shared__ float sred[8];
    __shared__ float s_scale;
    if ((threadIdx.x & 31) == 0) sred[threadIdx.x >> 5] = ss;
    __syncthreads();
    if (threadIdx.x == 0) {
        float tot = 0.f;
        #pragma unroll
        for (int i = 0; i < 8; i++) tot += sred[i];
        s_scale = rsqrtf(tot * (1.f/DM) + EPSV);
    }
    __syncthreads();
    float sc = s_scale;
    float* orow = out + (long)m*DM;
    orow[threadIdx.x]       = v0 * sc * w[threadIdx.x];
    orow[threadIdx.x + 256] = v1 * sc * w[threadIdx.x + 256];
    orow[threadIdx.x + 512] = v2 * sc * w[threadIdx.x + 512];
}

// ---------------- SGEMM NT: C[M,N] = A[M,K] * B[N,K]^T (128x128x8, 8x8 microtile) ----------------
// EPI: 0 = store, 1 = softplus(acc + bias[n]), 2 = C += acc (residual)
template<int EPI>
__global__ __launch_bounds__(256, 2)
void sgemm_nt(const float* __restrict__ A, const float* __restrict__ B,
              float* __restrict__ C, const float* __restrict__ bias,
              int N, int K, int lda, int ldb, int ldc)
{
    __shared__ __align__(16) float As[8][128];
    __shared__ __align__(16) float Bs[8][128];

    const int tid  = threadIdx.x;
    const int bm   = blockIdx.y * 128;
    const int bn   = blockIdx.x * 128;
    const int arow = tid >> 1;
    const int acol = (tid & 1) << 2;
    const int ty   = tid >> 4;
    const int tx   = tid & 15;

    float acc[8][8];
    #pragma unroll
    for (int i = 0; i < 8; i++)
        #pragma unroll
        for (int j = 0; j < 8; j++) acc[i][j] = 0.f;

    const float* Aptr = A + (long)(bm + arow)*lda + acol;
    const float* Bptr = B + (long)(bn + arow)*ldb + acol;
    const bool bvalid = (bn + arow) < N;

    const int nk = K >> 3;
    float4 a_reg = *(const float4*)Aptr;
    float4 b_reg = bvalid ? *(const float4*)Bptr : make_float4(0.f,0.f,0.f,0.f);

    for (int kt = 0; kt < nk; kt++) {
        As[acol+0][arow] = a_reg.x; As[acol+1][arow] = a_reg.y;
        As[acol+2][arow] = a_reg.z; As[acol+3][arow] = a_reg.w;
        Bs[acol+0][arow] = b_reg.x; Bs[acol+1][arow] = b_reg.y;
        Bs[acol+2][arow] = b_reg.z; Bs[acol+3][arow] = b_reg.w;
        __syncthreads();
        if (kt + 1 < nk) {
            a_reg = *(const float4*)(Aptr + (kt+1)*8);
            b_reg = bvalid ? *(const float4*)(Bptr + (kt+1)*8) : make_float4(0.f,0.f,0.f,0.f);
        }
        #pragma unroll
        for (int k = 0; k < 8; k++) {
            float4 a0 = *(const float4*)&As[k][ty*8];
            float4 a1 = *(const float4*)&As[k][ty*8 + 4];
            float4 b0 = *(const float4*)&Bs[k][tx*8];
            float4 b1 = *(const float4*)&Bs[k][tx*8 + 4];
            float av[8] = {a0.x,a0.y,a0.z,a0.w,a1.x,a1.y,a1.z,a1.w};
            float bv[8] = {b0.x,b0.y,b0.z,b0.w,b1.x,b1.y,b1.z,b1.w};
            #pragma unroll
            for (int i = 0; i < 8; i++)
                #pragma unroll
                for (int j = 0; j < 8; j++)
                    acc[i][j] += av[i]*bv[j];
        }
        __syncthreads();
    }

    #pragma unroll
    for (int i = 0; i < 8; i++) {
        long row = bm + ty*8 + i;
        #pragma unroll
        for (int j = 0; j < 8; j++) {
            int col = bn + tx*8 + j;
            if (col < N) {
                float v = acc[i][j];
                if (EPI == 1) {
                    v += bias[col];
                    v = (v > 20.f) ? v : log1pf(__expf(v));   // softplus
                    C[row*ldc + col] = v;
                } else if (EPI == 2) {
                    C[row*ldc + col] += v;
                } else {
                    C[row*ldc + col] = v;
                }
            }
        }
    }
}

// ---------------- depthwise causal conv (k=4) + silu, over xz[:, :DI] ----------------
__global__ void conv_silu_k(const float* __restrict__ xz, const float* __restrict__ cw,
                            const float* __restrict__ cb, float* __restrict__ xx)
{
    long idx = (long)blockIdx.x*256 + threadIdx.x;      // over MROWS*DI
    int d = (int)(idx % DI);
    long bt = idx / DI;
    int t = (int)(bt % TLEN);
    long b = bt / TLEN;
    float acc = cb[d];
    #pragma unroll
    for (int k = 0; k < 4; k++) {
        int ts = t - 3 + k;
        if (ts >= 0) acc += cw[d*4 + k] * xz[(b*TLEN + ts)*(2L*DI) + d];
    }
    float s = acc / (1.f + __expf(-acc));
    xx[idx] = s;
}

// ---------------- selective scan, phase A: per-chunk (P, Q) composition ----------------
// grid: (DI/256, NCHUNK, BSZ)
__global__ void scan_phaseA(const float* __restrict__ delta, const float* __restrict__ xx,
                            const float* __restrict__ dbc,  const float* __restrict__ A_log_l,
                            float* __restrict__ Pbuf, float* __restrict__ Qbuf)
{
    const int d = blockIdx.x*256 + threadIdx.x;
    const int c = blockIdx.y, b = blockIdx.z;
    __shared__ __align__(16) float sB[CLEN][16];
    const long rbase = (long)b*TLEN + c*CLEN;
    for (int i = threadIdx.x; i < CLEN*16; i += 256) {
        int tt = i >> 4, n = i & 15;
        sB[tt][n] = dbc[(rbase + tt)*80 + 48 + n];
    }
    __syncthreads();

    float An[16];
    #pragma unroll
    for (int n = 0; n < 16; n++)
        An[n] = -__expf(A_log_l[d*16 + n]) * 1.44269504f;   // A * log2(e)

    float P[16], Q[16];
    #pragma unroll
    for (int n = 0; n < 16; n++) { P[n] = 1.f; Q[n] = 0.f; }

    const long off = rbase*DI + d;
    const float* dp = delta + off;
    const float* xp = xx + off;

    for (int tt = 0; tt < CLEN; tt++) {
        float dl  = dp[(long)tt*DI];
        float xv  = xp[(long)tt*DI];
        float dtx = dl * xv;
        float4 b0 = *(const float4*)&sB[tt][0];
        float4 b1 = *(const float4*)&sB[tt][4];
        float4 b2 = *(const float4*)&sB[tt][8];
        float4 b3 = *(const float4*)&sB[tt][12];
        float bv[16] = {b0.x,b0.y,b0.z,b0.w, b1.x,b1.y,b1.z,b1.w,
                        b2.x,b2.y,b2.z,b2.w, b3.x,b3.y,b3.z,b3.w};
        #pragma unroll
        for (int n = 0; n < 16; n++) {
            float a = ex2f(dl * An[n]);
            P[n] *= a;
            Q[n] = a*Q[n] + dtx*bv[n];
        }
    }
    long base = (((long)b*NCHUNK + c)*DI + d) * 16;
    #pragma unroll
    for (int n = 0; n < 16; n += 4) {
        *(float4*)&Pbuf[base + n] = make_float4(P[n],P[n+1],P[n+2],P[n+3]);
        *(float4*)&Qbuf[base + n] = make_float4(Q[n],Q[n+1],Q[n+2],Q[n+3]);
    }
}

// ---------------- scan phase B: sequential chunk combine, emit chunk-entry states ----------------
__global__ void scan_phaseB(const float* __restrict__ Pbuf, const float* __restrict__ Qbuf,
                            float* __restrict__ hs)
{
    int idx = blockIdx.x*256 + threadIdx.x;   // over BSZ*DI = 6144
    int b = idx / DI, d = idx % DI;
    float h[16];
    #pragma unroll
    for (int n = 0; n < 16; n++) h[n] = 0.f;
    for (int c = 0; c < NCHUNK; c++) {
        long obase = (((long)c*BSZ + b)*DI + d) * 16;
        #pragma unroll
        for (int n = 0; n < 16; n += 4)
            *(float4*)&hs[obase + n] = make_float4(h[n],h[n+1],h[n+2],h[n+3]);
        long ibase = (((long)b*NCHUNK + c)*DI + d) * 16;
        #pragma unroll
        for (int n = 0; n < 16; n += 4) {
            float4 p = *(const float4*)&Pbuf[ibase + n];
            float4 q = *(const float4*)&Qbuf[ibase + n];
            h[n+0] = p.x*h[n+0] + q.x;
            h[n+1] = p.y*h[n+1] + q.y;
            h[n+2] = p.z*h[n+2] + q.z;
            h[n+3] = p.w*h[n+3] + q.w;
        }
    }
}

// ---------------- scan phase C: replay + y = dot(h,C) + D*x, gated by silu(z) ----------------
// grid: (DI/256, NCHUNK, BSZ)
__global__ void scan_phaseC(const float* __restrict__ delta, const float* __restrict__ xx,
                            const float* __restrict__ dbc,  const float* __restrict__ xz,
                            const float* __restrict__ A_log_l, const float* __restrict__ Dsk_l,
                            const float* __restrict__ hs, float* __restrict__ y)
{
    const int d = blockIdx.x*256 + threadIdx.x;
    const int c = blockIdx.y, b = blockIdx.z;
    __shared__ __align__(16) float sB[CLEN][16];
    __shared__ __align__(16) float sC[CLEN][16];
    const long rbase = (long)b*TLEN + c*CLEN;
    for (int i = threadIdx.x; i < CLEN*32; i += 256) {
        int tt = i >> 5, k = i & 31;
        float v = dbc[(rbase + tt)*80 + 48 + k];
        if (k < 16) sB[tt][k] = v; else sC[tt][k-16] = v;
    }
    __syncthreads();

    float An[16];
    #pragma unroll
    for (int n = 0; n < 16; n++)
        An[n] = -__expf(A_log_l[d*16 + n]) * 1.44269504f;

    float h[16];
    const float* hsp = hs + (((long)c*BSZ + b)*DI + d) * 16;
    #pragma unroll
    for (int n = 0; n < 16; n += 4) {
        float4 v = *(const float4*)&hsp[n];
        h[n] = v.x; h[n+1] = v.y; h[n+2] = v.z; h[n+3] = v.w;
    }
    const float Dv = Dsk_l[d];
    const long off = rbase*DI + d;
    const float* dp = delta + off;
    const float* xp = xx + off;
    const float* zp = xz + rbase*(2L*DI) + DI + d;
    float* yp = y + off;

    for (int tt = 0; tt < CLEN; tt++) {
        float dl  = dp[(long)tt*DI];
        float xv  = xp[(long)tt*DI];
        float dtx = dl * xv;
        float4 b0 = *(const float4*)&sB[tt][0];
        float4 b1 = *(const float4*)&sB[tt][4];
        float4 b2 = *(const float4*)&sB[tt][8];
        float4 b3 = *(const float4*)&sB[tt][12];
        float4 c0 = *(const float4*)&sC[tt][0];
        float4 c1 = *(const float4*)&sC[tt][4];
        float4 c2 = *(const float4*)&sC[tt][8];
        float4 c3 = *(const float4*)&sC[tt][12];
        float bv[16] = {b0.x,b0.y,b0.z,b0.w, b1.x,b1.y,b1.z,b1.w,
                        b2.x,b2.y,b2.z,b2.w, b3.x,b3.y,b3.z,b3.w};
        float cv[16] = {c0.x,c0.y,c0.z,c0.w, c1.x,c1.y,c1.z,c1.w,
                        c2.x,c2.y,c2.z,c2.w, c3.x,c3.y,c3.z,c3.w};
        float yacc = 0.f;
        #pragma unroll
        for (int n = 0; n < 16; n++) {
            float a = ex2f(dl * An[n]);
            h[n] = a*h[n] + dtx*bv[n];
            yacc += h[n]*cv[n];
        }
        float yd = yacc + Dv*xv;
        float zv = zp[(long)tt*(2L*DI)];
        float gate = zv / (1.f + __expf(-zv));   // silu(z)
        yp[(long)tt*DI] = yd * gate;
    }
}

// ---------------- final: rmsnorm + head in one pass ----------------
__global__ void head_k(const float* __restrict__ h, const float* __restrict__ nw,
                       const float* __restrict__ hw, const float* __restrict__ hb,
                       float* __restrict__ out)
{
    int m = blockIdx.x;
    const float* row = h + (long)m*DM;
    float ss = 0.f, dp = 0.f;
    #pragma unroll
    for (int r = 0; r < 3; r++) {
        int i = threadIdx.x + r*256;
        float v = row[i];
        ss += v*v;
        dp += v * nw[i] * hw[i];
    }
    #pragma unroll
    for (int o = 16; o > 0; o >>= 1) {
        ss += __shfl_down_sync(0xffffffffu, ss, o);
        dp += __shfl_down_sync(0xffffffffu, dp, o);
    }
    __shared__ float s_ss[8], s_dp[8];
    if ((threadIdx.x & 31) == 0) { s_ss[threadIdx.x>>5] = ss; s_dp[threadIdx.x>>5] = dp; }
    __syncthreads();
    if (threadIdx.x == 0) {
        float tss = 0.f, tdp = 0.f;
        #pragma unroll
        for (int i = 0; i < 8; i++) { tss += s_ss[i]; tdp += s_dp[i]; }
        out[m] = tdp * rsqrtf(tss * (1.f/DM) + EPSV) + hb[0];
    }
}

// ---------------- launcher ----------------
extern "C" void kernel_launch(void* const* d_in, const int* in_sizes, int n_in,
                              void* d_out, int out_size)
{
    const float* x         = (const float*)d_in[0];
    const float* inp_w     = (const float*)d_in[1];
    const float* inp_b     = (const float*)d_in[2];
    const float* in_proj_w = (const float*)d_in[3];
    const float* conv_w    = (const float*)d_in[4];
    const float* conv_b    = (const float*)d_in[5];
    const float* x_proj_w  = (const float*)d_in[6];
    const float* dt_proj_w = (const float*)d_in[7];
    const float* dt_proj_b = (const float*)d_in[8];
    const float* A_log     = (const float*)d_in[9];
    const float* D_skip    = (const float*)d_in[10];
    const float* out_proj_w= (const float*)d_in[11];
    const float* ln_w      = (const float*)d_in[12];
    const float* norm_w    = (const float*)d_in[13];
    const float* head_w    = (const float*)d_in[14];
    const float* head_b    = (const float*)d_in[15];

    float* buf = nullptr;
    cudaGetSymbolAddress((void**)&buf, g_buf);
    float* h     = buf + OFF_H;
    float* xn    = buf + OFF_XN;
    float* xz    = buf + OFF_XZ;
    float* xx    = buf + OFF_XX;
    float* dbc   = buf + OFF_DBC;
    float* delta = buf + OFF_DELTA;
    float* yb    = buf + OFF_Y;
    float* Pb    = buf + OFF_P;
    float* Qb    = buf + OFF_Q;
    float* hsb   = buf + OFF_HS;

    input_proj_k<<<MROWS, 256>>>(x, inp_w, inp_b, h);

    for (int l = 0; l < NLAYERS; l++) {
        const float* inw  = in_proj_w + (long)l*2*DI*DM;
        const float* cw   = conv_w    + (long)l*DI*4;
        const float* cb   = conv_b    + (long)l*DI;
        const float* xpw  = x_proj_w  + (long)l*80*DI;
        const float* dtw  = dt_proj_w + (long)l*DI*DTR;
        const float* dtb  = dt_proj_b + (long)l*DI;
        const float* Al   = A_log     + (long)l*DI*DS;
        const float* Dsk  = D_skip    + (long)l*DI;
        const float* opw  = out_proj_w+ (long)l*DM*DI;
        const float* lnw  = ln_w      + (long)l*DM;

        rmsnorm_k<<<MROWS, 256>>>(h, lnw, xn);

        // xz[4096,3072] = xn[4096,768] @ inw[3072,768]^T
        sgemm_nt<0><<<dim3((2*DI)/128, MROWS/128), 256>>>(xn, inw, xz, nullptr,
                                                          2*DI, DM, DM, DM, 2*DI);
        conv_silu_k<<<(MROWS*DI)/256, 256>>>(xz, cw, cb, xx);

        // dbc[4096,80] = xx[4096,1536] @ xpw[80,1536]^T
        sgemm_nt<0><<<dim3(1, MROWS/128), 256>>>(xx, xpw, dbc, nullptr,
                                                 80, DI, DI, DI, 80);
        // delta[4096,1536] = softplus(dbc[:, :48] @ dtw[1536,48]^T + dtb)
        sgemm_nt<1><<<dim3(DI/128, MROWS/128), 256>>>(dbc, dtw, delta, dtb,
                                                      DI, DTR, 80, DTR, DI);

        scan_phaseA<<<dim3(DI/256, NCHUNK, BSZ), 256>>>(delta, xx, dbc, Al, Pb, Qb);
        scan_phaseB<<<(BSZ*DI)/256, 256>>>(Pb, Qb, hsb);
        scan_phaseC<<<dim3(DI/256, NCHUNK, BSZ), 256>>>(delta, xx, dbc, xz, Al, Dsk, hsb, yb);

        // h[4096,768] += yb[4096,1536] @ opw[768,1536]^T
        sgemm_nt<2><<<dim3(DM/128, MROWS/128), 256>>>(yb, opw, h, nullptr,
                                                      DM, DI, DI, DI, DM);
    }

    head_k<<<MROWS, 256>>>(h, norm_w, head_w, head_b, (float*)d_out);
}